// round 3
// baseline (speedup 1.0000x reference)
#include <cuda_runtime.h>
#include <math.h>
#include <stdint.h>

#define NNODES 50000
#define NEDGES 800000
#define EDIM   128
#define FW     640   // F row: [k(128) | v(128) | q(128) | qe0(128) | qe1(128)]
#define GW     384   // G row: [accv(128) | acce_h0(128) | acce_h1(128)]
#define KBACK  512

// ---------------- device scratch (no allocs allowed) ----------------
__device__ float g_F[(size_t)NNODES * FW];      // 128 MB
__device__ float g_G[(size_t)NNODES * GW];      // 76.8 MB
__device__ int   g_deg[NNODES];
__device__ int   g_rowptr[NNODES + 1];
__device__ int   g_cursor[NNODES];
__device__ int   g_eids[NEDGES];
__device__ float g_Wbig[EDIM * FW];             // front weights [k][c]
__device__ float g_bbig[FW];
__device__ float g_Wback[KBACK * EDIM];         // back weights [k][o]
__device__ float g_bback[EDIM];

// ---------------- weight preprocessing ----------------
// Wbig columns: 0..127 -> Wk ; 128..255 -> Wv ; 256..383 -> Wq ;
// 384+h*128+d -> sum_c Wq[r,h*64+c]*We[d,h*64+c]  (qe = We_h @ q)
// Wback rows: 0..127 accv path (Wproj) ; 128..383 acce path (We_h@Wproj_h) ;
// 384..511 skip path (Wskip@Wproj). bback = bskip@Wproj + bproj.
__global__ void prep_weights(
    const float* __restrict__ Wq, const float* __restrict__ bq,
    const float* __restrict__ Wk, const float* __restrict__ bk,
    const float* __restrict__ Wv, const float* __restrict__ bv,
    const float* __restrict__ We,
    const float* __restrict__ Wskip, const float* __restrict__ bskip,
    const float* __restrict__ Wproj, const float* __restrict__ bproj)
{
    int t = blockIdx.x * blockDim.x + threadIdx.x;
    if (t < 81920) {  // Wbig: 128 x 640
        int r = t / 640, c = t % 640;
        float val;
        if (c < 128)      val = Wk[r * 128 + c];
        else if (c < 256) val = Wv[r * 128 + (c - 128)];
        else if (c < 384) val = Wq[r * 128 + (c - 256)];
        else {
            int cc = c - 384, h = cc >> 7, d = cc & 127;
            float s = 0.f;
            #pragma unroll 8
            for (int ci = 0; ci < 64; ci++)
                s += Wq[r * 128 + h * 64 + ci] * We[d * 128 + h * 64 + ci];
            val = s;
        }
        g_Wbig[r * 640 + c] = val;
        return;
    }
    t -= 81920;
    if (t < 640) {  // bbig
        int c = t; float val;
        if (c < 128)      val = bk[c];
        else if (c < 256) val = bv[c - 128];
        else if (c < 384) val = bq[c - 256];
        else {
            int cc = c - 384, h = cc >> 7, d = cc & 127;
            float s = 0.f;
            #pragma unroll 8
            for (int ci = 0; ci < 64; ci++)
                s += bq[h * 64 + ci] * We[d * 128 + h * 64 + ci];
            val = s;
        }
        g_bbig[c] = val;
        return;
    }
    t -= 640;
    if (t < 65536) {  // Wback: 512 x 128
        int k = t / 128, o = t % 128;
        float val;
        if (k < 128) {
            val = Wproj[k * 128 + o];
        } else if (k < 384) {
            int kk = k - 128, h = kk >> 7, d = kk & 127;
            float s = 0.f;
            #pragma unroll 8
            for (int ci = 0; ci < 64; ci++)
                s += We[d * 128 + h * 64 + ci] * Wproj[(h * 64 + ci) * 128 + o];
            val = s;
        } else {
            int r = k - 384;
            float s = 0.f;
            #pragma unroll 8
            for (int m = 0; m < 128; m++)
                s += Wskip[r * 128 + m] * Wproj[m * 128 + o];
            val = s;
        }
        g_Wback[k * 128 + o] = val;
        return;
    }
    t -= 65536;
    if (t < 128) {  // bback
        int o = t;
        float s = bproj[o];
        #pragma unroll 8
        for (int m = 0; m < 128; m++)
            s += bskip[m] * Wproj[m * 128 + o];
        g_bback[o] = s;
    }
}

// ---------------- tiled SGEMM (fp32) ----------------
// MODE 0: g_F = X[N,128] @ g_Wbig[128,640] + g_bbig
// MODE 1: Out = [g_G(384) | X(128)] @ g_Wback[512,128] + g_bback
template <int MODE>
__global__ void __launch_bounds__(256) sgemm_kernel(
    const float* __restrict__ X, float* __restrict__ Out)
{
    constexpr int K  = (MODE == 0) ? 128 : 512;
    constexpr int NC = (MODE == 0) ? 640 : 128;
    __shared__ float As[16][132];
    __shared__ float Bs[16][64];
    const float* W    = (MODE == 0) ? g_Wbig : g_Wback;
    const float* bias = (MODE == 0) ? g_bbig : g_bback;
    float* C          = (MODE == 0) ? g_F    : Out;

    int tid = threadIdx.x;
    int tx = tid & 15, ty = tid >> 4;
    int m0 = blockIdx.y * 128, n0 = blockIdx.x * 64;

    float acc[8][4];
    #pragma unroll
    for (int i = 0; i < 8; i++)
        #pragma unroll
        for (int j = 0; j < 4; j++) acc[i][j] = 0.f;

    for (int kt = 0; kt < K; kt += 16) {
        #pragma unroll
        for (int i = 0; i < 2; i++) {
            int lin = tid + i * 256;
            int row = lin >> 2;
            int c4  = (lin & 3) << 2;
            int grow = m0 + row;
            float4 v = make_float4(0.f, 0.f, 0.f, 0.f);
            if (grow < NNODES) {
                int kk = kt + c4;
                const float* src;
                if (MODE == 0) {
                    src = X + (size_t)grow * 128 + kk;
                } else {
                    src = (kk < 384) ? (g_G + (size_t)grow * 384 + kk)
                                     : (X + (size_t)grow * 128 + (kk - 384));
                }
                v = *(const float4*)src;
            }
            As[c4 + 0][row] = v.x; As[c4 + 1][row] = v.y;
            As[c4 + 2][row] = v.z; As[c4 + 3][row] = v.w;
        }
        {
            int wr = tid >> 4, wc = (tid & 15) << 2;
            *(float4*)&Bs[wr][wc] =
                *(const float4*)(W + (size_t)(kt + wr) * NC + n0 + wc);
        }
        __syncthreads();
        #pragma unroll
        for (int k = 0; k < 16; k++) {
            float4 a0 = *(const float4*)&As[k][ty * 8];
            float4 a1 = *(const float4*)&As[k][ty * 8 + 4];
            float4 b  = *(const float4*)&Bs[k][tx * 4];
            float av[8] = {a0.x, a0.y, a0.z, a0.w, a1.x, a1.y, a1.z, a1.w};
            #pragma unroll
            for (int im = 0; im < 8; im++) {
                acc[im][0] += av[im] * b.x;
                acc[im][1] += av[im] * b.y;
                acc[im][2] += av[im] * b.z;
                acc[im][3] += av[im] * b.w;
            }
        }
        __syncthreads();
    }
    float4 bv4 = *(const float4*)(bias + n0 + tx * 4);
    #pragma unroll
    for (int im = 0; im < 8; im++) {
        int row = m0 + ty * 8 + im;
        if (row < NNODES) {
            float4 o;
            o.x = acc[im][0] + bv4.x; o.y = acc[im][1] + bv4.y;
            o.z = acc[im][2] + bv4.z; o.w = acc[im][3] + bv4.w;
            *(float4*)(C + (size_t)row * NC + n0 + tx * 4) = o;
        }
    }
}

// ---------------- CSR build ----------------
__global__ void zero_deg_kernel()
{
    int t = blockIdx.x * blockDim.x + threadIdx.x;
    if (t < NNODES) g_deg[t] = 0;
}

__global__ void hist_kernel(const int* __restrict__ dst)
{
    int t = blockIdx.x * blockDim.x + threadIdx.x;
    if (t < NEDGES) atomicAdd(&g_deg[dst[t]], 1);
}

__global__ void scan_kernel()
{
    __shared__ int sm[1024];
    int t = threadIdx.x;
    const int CH = (NNODES + 1023) / 1024;  // 49
    int lo = t * CH;
    int hi = min(lo + CH, NNODES);
    int s = 0;
    for (int i = lo; i < hi; i++) s += g_deg[i];
    sm[t] = s;
    __syncthreads();
    for (int off = 1; off < 1024; off <<= 1) {
        int y = (t >= off) ? sm[t - off] : 0;
        __syncthreads();
        sm[t] += y;
        __syncthreads();
    }
    int run = sm[t] - s;  // exclusive prefix
    for (int i = lo; i < hi; i++) {
        g_rowptr[i] = run;
        g_cursor[i] = run;
        run += g_deg[i];
    }
    if (t == 1023) g_rowptr[NNODES] = sm[1023];
}

__global__ void scatter_kernel(const int* __restrict__ dst)
{
    int t = blockIdx.x * blockDim.x + threadIdx.x;
    if (t < NEDGES) {
        int d = dst[t];
        int pos = atomicAdd(&g_cursor[d], 1);
        g_eids[pos] = t;
    }
}

// ---------------- per-node attention (1 warp / node, online softmax) ----
// lane l owns floats [4l..4l+3] of each 128-wide row; head = l/16 for q/k/v.
__global__ void __launch_bounds__(256) edge_attn_kernel(
    const float* __restrict__ edge_attr, const int* __restrict__ srcp)
{
    int gw   = (blockIdx.x * blockDim.x + threadIdx.x) >> 5;
    int lane = threadIdx.x & 31;
    if (gw >= NNODES) return;
    int i = gw;
    int base = g_rowptr[i], end = g_rowptr[i + 1];

    const float* Fi = g_F + (size_t)i * FW;
    float4 q   = *(const float4*)(Fi + 256 + 4 * lane);
    float4 qe0 = *(const float4*)(Fi + 384 + 4 * lane);
    float4 qe1 = *(const float4*)(Fi + 512 + 4 * lane);

    float4 accv = make_float4(0.f, 0.f, 0.f, 0.f);
    float4 ae0  = make_float4(0.f, 0.f, 0.f, 0.f);
    float4 ae1  = make_float4(0.f, 0.f, 0.f, 0.f);
    float den0 = 0.f, den1 = 0.f;
    float curmax = -3.0e38f;  // per-lane max of this lane's head
    const unsigned FULL = 0xffffffffu;

    int e_next = 0, sj_next = 0;
    if (base < end) { e_next = g_eids[base]; sj_next = srcp[e_next]; }

    for (int s = base; s < end; s++) {
        int e = e_next, sj = sj_next;
        if (s + 1 < end) { e_next = g_eids[s + 1]; sj_next = srcp[e_next]; }

        const float* ep = edge_attr + (size_t)e * EDIM + 4 * lane;
        const float* fp = g_F + (size_t)sj * FW + 4 * lane;
        float4 ea = *(const float4*)ep;
        float4 kk = *(const float4*)fp;          // k section (offset 0)
        float4 vv = *(const float4*)(fp + 128);  // v section

        float pqk = q.x * kk.x + q.y * kk.y + q.z * kk.z + q.w * kk.w;
        float p0 = ea.x * qe0.x + ea.y * qe0.y + ea.z * qe0.z + ea.w * qe0.w;
        float p1 = ea.x * qe1.x + ea.y * qe1.y + ea.z * qe1.z + ea.w * qe1.w;
        #pragma unroll
        for (int off = 16; off >= 1; off >>= 1) {
            p0 += __shfl_xor_sync(FULL, p0, off);
            p1 += __shfl_xor_sync(FULL, p1, off);
        }
        #pragma unroll
        for (int off = 8; off >= 1; off >>= 1)
            pqk += __shfl_xor_sync(FULL, pqk, off);

        float alpha = (pqk + ((lane < 16) ? p0 : p1)) * 0.125f;

        // online softmax (per head; alpha identical across the 16-lane half)
        float newmax = fmaxf(curmax, alpha);
        float scale  = __expf(curmax - newmax);  // first edge: exp(-3e38)=0
        float p      = __expf(alpha - newmax);
        curmax = newmax;

        float s0  = __shfl_sync(FULL, scale, 0);
        float s1  = __shfl_sync(FULL, scale, 16);
        float p0b = __shfl_sync(FULL, p, 0);
        float p1b = __shfl_sync(FULL, p, 16);
        float sh = (lane < 16) ? s0 : s1;
        float ph = (lane < 16) ? p0b : p1b;

        den0 = den0 * s0 + p0b;
        den1 = den1 * s1 + p1b;
        accv.x = accv.x * sh + vv.x * ph; accv.y = accv.y * sh + vv.y * ph;
        accv.z = accv.z * sh + vv.z * ph; accv.w = accv.w * sh + vv.w * ph;
        ae0.x = ae0.x * s0 + ea.x * p0b; ae0.y = ae0.y * s0 + ea.y * p0b;
        ae0.z = ae0.z * s0 + ea.z * p0b; ae0.w = ae0.w * s0 + ea.w * p0b;
        ae1.x = ae1.x * s1 + ea.x * p1b; ae1.y = ae1.y * s1 + ea.y * p1b;
        ae1.z = ae1.z * s1 + ea.z * p1b; ae1.w = ae1.w * s1 + ea.w * p1b;
    }

    float r0 = (den0 > 0.f) ? (1.f / den0) : 0.f;
    float r1 = (den1 > 0.f) ? (1.f / den1) : 0.f;
    float rh = (lane < 16) ? r0 : r1;

    float* Gi = g_G + (size_t)i * GW;
    float4 o;
    o.x = accv.x * rh; o.y = accv.y * rh; o.z = accv.z * rh; o.w = accv.w * rh;
    *(float4*)(Gi + 4 * lane) = o;
    o.x = ae0.x * r0; o.y = ae0.y * r0; o.z = ae0.z * r0; o.w = ae0.w * r0;
    *(float4*)(Gi + 128 + 4 * lane) = o;
    o.x = ae1.x * r1; o.y = ae1.y * r1; o.z = ae1.z * r1; o.w = ae1.w * r1;
    *(float4*)(Gi + 256 + 4 * lane) = o;
}

// ---------------- launch ----------------
extern "C" void kernel_launch(void* const* d_in, const int* in_sizes, int n_in,
                              void* d_out, int out_size)
{
    const float* x         = (const float*)d_in[0];
    const float* edge_attr = (const float*)d_in[1];
    const float* Wq    = (const float*)d_in[2];
    const float* bq    = (const float*)d_in[3];
    const float* Wk    = (const float*)d_in[4];
    const float* bk    = (const float*)d_in[5];
    const float* Wv    = (const float*)d_in[6];
    const float* bv    = (const float*)d_in[7];
    const float* We    = (const float*)d_in[8];
    const float* Wskip = (const float*)d_in[9];
    const float* bskip = (const float*)d_in[10];
    const float* Wproj = (const float*)d_in[11];
    const float* bproj = (const float*)d_in[12];
    const int*   eidx  = (const int*)d_in[13];
    const int*   srcp  = eidx;            // edge_index[0] = source j
    const int*   dstp  = eidx + NEDGES;   // edge_index[1] = target i

    // 1. fold weights
    prep_weights<<<(148224 + 255) / 256, 256>>>(Wq, bq, Wk, bk, Wv, bv, We,
                                                Wskip, bskip, Wproj, bproj);
    // 2. front GEMM: F = x @ Wbig + bbig   ([k|v|q|qe0|qe1])
    sgemm_kernel<0><<<dim3(10, (NNODES + 127) / 128), 256>>>(x, nullptr);
    // 3. CSR build (dst-grouped edge lists)
    zero_deg_kernel<<<(NNODES + 255) / 256, 256>>>();
    hist_kernel<<<(NEDGES + 255) / 256, 256>>>(dstp);
    scan_kernel<<<1, 1024>>>();
    scatter_kernel<<<(NEDGES + 255) / 256, 256>>>(dstp);
    // 4. per-node attention -> G = [accv | acce_h0 | acce_h1] (softmax-normalized)
    edge_attn_kernel<<<(NNODES * 32 + 255) / 256, 256>>>(edge_attr, srcp);
    // 5. back GEMM: out = [G | x] @ Wback + bback
    sgemm_kernel<1><<<dim3(2, (NNODES + 127) / 128), 256>>>(x, (float*)d_out);
}

// round 5
// speedup vs baseline: 1.2025x; 1.2025x over previous
#include <cuda_runtime.h>
#include <cuda_bf16.h>
#include <math.h>
#include <stdint.h>

#define NNODES 50000
#define NEDGES 800000
#define EDIM   128
#define FW     640   // F row: [k(128) | v(128) | q(128) | qe0(128) | qe1(128)]
#define GW     384   // G row: [accv(128) | acce_h0(128) | acce_h1(128)]

// ---------------- device scratch (no allocs allowed) ----------------
__device__ float g_F[(size_t)NNODES * FW];      // 128 MB
__device__ float g_G[(size_t)NNODES * GW];      // 76.8 MB
__device__ int   g_deg[NNODES];
__device__ int   g_rowptr[NNODES + 1];
__device__ int   g_cursor[NNODES];
__device__ int   g_eids[NEDGES];
__device__ float g_bbig[FW];
__device__ float g_bback[EDIM];
// split-bf16 weights, [out][k] K-major (mma.sync "col" B operand)
__device__ __nv_bfloat16 g_BFt_hi[640 * 128];
__device__ __nv_bfloat16 g_BFt_lo[640 * 128];
__device__ __nv_bfloat16 g_BBt_hi[128 * 512];
__device__ __nv_bfloat16 g_BBt_lo[128 * 512];

// ================= helpers =================
__device__ __forceinline__ uint32_t smem_u32(const void* p) {
    uint32_t a;
    asm("{ .reg .u64 t; cvta.to.shared.u64 t, %1; cvt.u32.u64 %0, t; }"
        : "=r"(a) : "l"(p));
    return a;
}
__device__ __forceinline__ void split2(float a, __nv_bfloat16& h, __nv_bfloat16& l)
{
    h = __float2bfloat16(a);
    l = __float2bfloat16(a - __bfloat162float(h));
}
__device__ __forceinline__ void ldsm4(uint32_t* r, uint32_t addr) {
    asm volatile("ldmatrix.sync.aligned.m8n8.x4.shared.b16 {%0,%1,%2,%3}, [%4];"
        : "=r"(r[0]), "=r"(r[1]), "=r"(r[2]), "=r"(r[3]) : "r"(addr));
}
__device__ __forceinline__ void ldsm2(uint32_t* r, uint32_t addr) {
    asm volatile("ldmatrix.sync.aligned.m8n8.x2.shared.b16 {%0,%1}, [%2];"
        : "=r"(r[0]), "=r"(r[1]) : "r"(addr));
}
__device__ __forceinline__ void mma16816(float* c, const uint32_t* a, const uint32_t* b) {
    asm volatile("mma.sync.aligned.m16n8k16.row.col.f32.bf16.bf16.f32 "
        "{%0,%1,%2,%3}, {%4,%5,%6,%7}, {%8,%9}, {%0,%1,%2,%3};"
        : "+f"(c[0]), "+f"(c[1]), "+f"(c[2]), "+f"(c[3])
        : "r"(a[0]), "r"(a[1]), "r"(a[2]), "r"(a[3]), "r"(b[0]), "r"(b[1]));
}

// ---------------- weight preprocessing ----------------
// BFt (front B, [c 0..639][k 0..127]): c 0..127 -> Wk ; 128..255 -> Wv ;
// 256..383 -> Wq ; 384+h*128+d -> (We_h @ Wq_h)  (qe path).
// BBt (back B, [o 0..127][k 0..511]): k 0..127 accv (Wproj) ;
// 128..383 acce (We_h@Wproj_h) ; 384..511 skip (Wskip@Wproj).
__global__ void prep_weights(
    const float* __restrict__ Wq, const float* __restrict__ bq,
    const float* __restrict__ Wk, const float* __restrict__ bk,
    const float* __restrict__ Wv, const float* __restrict__ bv,
    const float* __restrict__ We,
    const float* __restrict__ Wskip, const float* __restrict__ bskip,
    const float* __restrict__ Wproj, const float* __restrict__ bproj)
{
    int t = blockIdx.x * blockDim.x + threadIdx.x;
    if (t < 81920) {  // front weights: (r=k, c=out)
        int r = t / 640, c = t % 640;
        float val;
        if (c < 128)      val = Wk[r * 128 + c];
        else if (c < 256) val = Wv[r * 128 + (c - 128)];
        else if (c < 384) val = Wq[r * 128 + (c - 256)];
        else {
            int cc = c - 384, h = cc >> 7, d = cc & 127;
            float s = 0.f;
            #pragma unroll 8
            for (int ci = 0; ci < 64; ci++)
                s += Wq[r * 128 + h * 64 + ci] * We[d * 128 + h * 64 + ci];
            val = s;
        }
        __nv_bfloat16 h16, l16; split2(val, h16, l16);
        g_BFt_hi[c * 128 + r] = h16;
        g_BFt_lo[c * 128 + r] = l16;
        return;
    }
    t -= 81920;
    if (t < 640) {  // bbig
        int c = t; float val;
        if (c < 128)      val = bk[c];
        else if (c < 256) val = bv[c - 128];
        else if (c < 384) val = bq[c - 256];
        else {
            int cc = c - 384, h = cc >> 7, d = cc & 127;
            float s = 0.f;
            #pragma unroll 8
            for (int ci = 0; ci < 64; ci++)
                s += bq[h * 64 + ci] * We[d * 128 + h * 64 + ci];
            val = s;
        }
        g_bbig[c] = val;
        return;
    }
    t -= 640;
    if (t < 65536) {  // back weights: (k, o)
        int k = t / 128, o = t % 128;
        float val;
        if (k < 128) {
            val = Wproj[k * 128 + o];
        } else if (k < 384) {
            int kk = k - 128, h = kk >> 7, d = kk & 127;
            float s = 0.f;
            #pragma unroll 8
            for (int ci = 0; ci < 64; ci++)
                s += We[d * 128 + h * 64 + ci] * Wproj[(h * 64 + ci) * 128 + o];
            val = s;
        } else {
            int r = k - 384;
            float s = 0.f;
            #pragma unroll 8
            for (int m = 0; m < 128; m++)
                s += Wskip[r * 128 + m] * Wproj[m * 128 + o];
            val = s;
        }
        __nv_bfloat16 h16, l16; split2(val, h16, l16);
        g_BBt_hi[o * 512 + k] = h16;
        g_BBt_lo[o * 512 + k] = l16;
        return;
    }
    t -= 65536;
    if (t < 128) {  // bback
        int o = t;
        float s = bproj[o];
        #pragma unroll 8
        for (int m = 0; m < 128; m++)
            s += bskip[m] * Wproj[m * 128 + o];
        g_bback[o] = s;
    }
}

// ================= HMMA (mma.sync) split-bf16 GEMM =================
// MODE 0: g_F[50000,640] = x[50000,128] @ BFt^T + bbig       (5 N-tiles of 128)
// MODE 1: out[50000,128] = [G(384)|x(128)] @ BBt^T + bback   (4 K-chunks of 128)
// smem tiles [128 rows][128 k] bf16, row stride 17 units of 16B (conflict-free).
#define OFF_AHI 0
#define OFF_ALO 34816
#define OFF_BHI 69632
#define OFF_BLO 104448
#define GEMM_SMEM 139264

template <int MODE>
__device__ __forceinline__ void load_A_tile(char* smem, const float* __restrict__ X,
                                            int m0, int kc, int tid)
{
    for (int it = tid; it < 2048; it += 256) {
        int row = it >> 4, u = it & 15, k = u * 8;
        int grow = m0 + row;
        float v[8];
        if (grow < NNODES) {
            const float* src;
            if (MODE == 0) {
                src = X + (size_t)grow * 128 + k;
            } else {
                int kg = kc * 128 + k;
                src = (kg < 384) ? (g_G + (size_t)grow * 384 + kg)
                                 : (X + (size_t)grow * 128 + (kg - 384));
            }
            float4 a = *(const float4*)src;
            float4 b = *(const float4*)(src + 4);
            v[0] = a.x; v[1] = a.y; v[2] = a.z; v[3] = a.w;
            v[4] = b.x; v[5] = b.y; v[6] = b.z; v[7] = b.w;
        } else {
            #pragma unroll
            for (int j = 0; j < 8; j++) v[j] = 0.f;
        }
        union { __nv_bfloat16 b[8]; uint4 u4; } H, L;
        #pragma unroll
        for (int j = 0; j < 8; j++) split2(v[j], H.b[j], L.b[j]);
        uint32_t off = (uint32_t)(row * 17 + u) * 16;
        *(uint4*)(smem + OFF_AHI + off) = H.u4;
        *(uint4*)(smem + OFF_ALO + off) = L.u4;
    }
}

template <int MODE>
__device__ __forceinline__ void load_B_tile(char* smem, int n0, int kc, int tid)
{
    const __nv_bfloat16* Bh = (MODE == 0) ? g_BFt_hi : g_BBt_hi;
    const __nv_bfloat16* Bl = (MODE == 0) ? g_BFt_lo : g_BBt_lo;
    constexpr int KB = (MODE == 0) ? 128 : 512;
    for (int it = tid; it < 2048; it += 256) {
        int n = it >> 4, u = it & 15;
        size_t si = (size_t)(n0 + n) * KB + (size_t)kc * 128 + u * 8;
        uint4 hv = *(const uint4*)(Bh + si);
        uint4 lv = *(const uint4*)(Bl + si);
        uint32_t off = (uint32_t)(n * 17 + u) * 16;
        *(uint4*)(smem + OFF_BHI + off) = hv;
        *(uint4*)(smem + OFF_BLO + off) = lv;
    }
}

__device__ __forceinline__ void mainloop(uint32_t sb, float acc[2][8][4],
                                         int wid, int lane)
{
    int wm = wid & 3, wn = wid >> 2;
    // ldmatrix lane->address mapping
    int arow  = wm * 32 + ((lane >> 3) & 1) * 8 + (lane & 7);  // + mt*16
    int acolh = lane >> 4;                                     // 16B-unit half
    int brow  = wn * 64 + (lane & 7);                          // + nt*8
    int bcolh = (lane >> 3) & 1;
    #pragma unroll
    for (int ks = 0; ks < 8; ks++) {
        uint32_t ah0[4], ah1[4], al0[4], al1[4];
        uint32_t au = (uint32_t)(ks * 2 + acolh);
        ldsm4(ah0, sb + OFF_AHI + ((uint32_t)arow * 17 + au) * 16);
        ldsm4(ah1, sb + OFF_AHI + ((uint32_t)(arow + 16) * 17 + au) * 16);
        ldsm4(al0, sb + OFF_ALO + ((uint32_t)arow * 17 + au) * 16);
        ldsm4(al1, sb + OFF_ALO + ((uint32_t)(arow + 16) * 17 + au) * 16);
        #pragma unroll
        for (int nt = 0; nt < 8; nt++) {
            uint32_t bh[2], bl[2];
            uint32_t boff = ((uint32_t)(brow + nt * 8) * 17 + ks * 2 + bcolh) * 16;
            ldsm2(bh, sb + OFF_BHI + boff);
            ldsm2(bl, sb + OFF_BLO + boff);
            mma16816(acc[0][nt], ah0, bh);
            mma16816(acc[1][nt], ah1, bh);
            mma16816(acc[0][nt], ah0, bl);
            mma16816(acc[1][nt], ah1, bl);
            mma16816(acc[0][nt], al0, bh);
            mma16816(acc[1][nt], al1, bh);
        }
    }
}

template <int MODE>
__device__ __forceinline__ void epilogue(float acc[2][8][4], float* __restrict__ C,
                                         const float* __restrict__ bias,
                                         int m0, int n0, int wid, int lane)
{
    constexpr int NC = (MODE == 0) ? 640 : 128;
    int wm = wid & 3, wn = wid >> 2;
    int r = m0 + wm * 32 + (lane >> 2);
    int cbase = n0 + wn * 64 + (lane & 3) * 2;
    #pragma unroll
    for (int mt = 0; mt < 2; mt++) {
        int r0 = r + mt * 16, r1 = r0 + 8;
        #pragma unroll
        for (int nt = 0; nt < 8; nt++) {
            int c = cbase + nt * 8;
            float2 bv = *(const float2*)(bias + c);
            if (r0 < NNODES) {
                float2 o = make_float2(acc[mt][nt][0] + bv.x, acc[mt][nt][1] + bv.y);
                *(float2*)(C + (size_t)r0 * NC + c) = o;
            }
            if (r1 < NNODES) {
                float2 o = make_float2(acc[mt][nt][2] + bv.x, acc[mt][nt][3] + bv.y);
                *(float2*)(C + (size_t)r1 * NC + c) = o;
            }
        }
    }
}

template <int MODE>
__global__ void __launch_bounds__(256, 1) hmma_gemm(const float* __restrict__ X,
                                                    float* __restrict__ Out)
{
    extern __shared__ char smem[];
    uint32_t sb = smem_u32(smem);
    int tid = threadIdx.x, wid = tid >> 5, lane = tid & 31;
    int m0 = blockIdx.x * 128;
    float* C = (MODE == 0) ? g_F : Out;
    const float* bias = (MODE == 0) ? g_bbig : g_bback;
    float acc[2][8][4];

    if (MODE == 0) {
        load_A_tile<0>(smem, X, m0, 0, tid);
        for (int ntb = 0; ntb < 5; ntb++) {
            __syncthreads();                // A ready / previous mainloop done
            load_B_tile<0>(smem, ntb * 128, 0, tid);
            __syncthreads();
            #pragma unroll
            for (int a = 0; a < 2; a++)
                #pragma unroll
                for (int b = 0; b < 8; b++)
                    #pragma unroll
                    for (int d = 0; d < 4; d++) acc[a][b][d] = 0.f;
            mainloop(sb, acc, wid, lane);
            epilogue<0>(acc, C, bias, m0, ntb * 128, wid, lane);
        }
    } else {
        #pragma unroll
        for (int a = 0; a < 2; a++)
            #pragma unroll
            for (int b = 0; b < 8; b++)
                #pragma unroll
                for (int d = 0; d < 4; d++) acc[a][b][d] = 0.f;
        for (int kc = 0; kc < 4; kc++) {
            if (kc) __syncthreads();        // previous mainloop done
            load_A_tile<1>(smem, X, m0, kc, tid);
            load_B_tile<1>(smem, 0, kc, tid);
            __syncthreads();
            mainloop(sb, acc, wid, lane);
        }
        epilogue<1>(acc, C, bias, m0, 0, wid, lane);
    }
}

// ---------------- CSR build ----------------
__global__ void zero_deg_kernel()
{
    int t = blockIdx.x * blockDim.x + threadIdx.x;
    if (t < NNODES) g_deg[t] = 0;
}

__global__ void hist_kernel(const int* __restrict__ dst)
{
    int t = blockIdx.x * blockDim.x + threadIdx.x;
    if (t < NEDGES) atomicAdd(&g_deg[dst[t]], 1);
}

__global__ void scan_kernel()
{
    __shared__ int sm[1024];
    int t = threadIdx.x;
    const int CH = (NNODES + 1023) / 1024;  // 49
    int lo = t * CH;
    int hi = min(lo + CH, NNODES);
    int s = 0;
    for (int i = lo; i < hi; i++) s += g_deg[i];
    sm[t] = s;
    __syncthreads();
    for (int off = 1; off < 1024; off <<= 1) {
        int y = (t >= off) ? sm[t - off] : 0;
        __syncthreads();
        sm[t] += y;
        __syncthreads();
    }
    int run = sm[t] - s;  // exclusive prefix
    for (int i = lo; i < hi; i++) {
        g_rowptr[i] = run;
        g_cursor[i] = run;
        run += g_deg[i];
    }
    if (t == 1023) g_rowptr[NNODES] = sm[1023];
}

__global__ void scatter_kernel(const int* __restrict__ dst)
{
    int t = blockIdx.x * blockDim.x + threadIdx.x;
    if (t < NEDGES) {
        int d = dst[t];
        int pos = atomicAdd(&g_cursor[d], 1);
        g_eids[pos] = t;
    }
}

// ---------------- per-node attention (1 warp / node, online softmax) ----
__global__ void __launch_bounds__(256) edge_attn_kernel(
    const float* __restrict__ edge_attr, const int* __restrict__ srcp)
{
    int gw   = (blockIdx.x * blockDim.x + threadIdx.x) >> 5;
    int lane = threadIdx.x & 31;
    if (gw >= NNODES) return;
    int i = gw;
    int base = g_rowptr[i], end = g_rowptr[i + 1];

    const float* Fi = g_F + (size_t)i * FW;
    float4 q   = *(const float4*)(Fi + 256 + 4 * lane);
    float4 qe0 = *(const float4*)(Fi + 384 + 4 * lane);
    float4 qe1 = *(const float4*)(Fi + 512 + 4 * lane);

    float4 accv = make_float4(0.f, 0.f, 0.f, 0.f);
    float4 ae0  = make_float4(0.f, 0.f, 0.f, 0.f);
    float4 ae1  = make_float4(0.f, 0.f, 0.f, 0.f);
    float den0 = 0.f, den1 = 0.f;
    float curmax = -3.0e38f;
    const unsigned FULL = 0xffffffffu;

    int e_next = 0, sj_next = 0;
    if (base < end) { e_next = g_eids[base]; sj_next = srcp[e_next]; }

    for (int s = base; s < end; s++) {
        int e = e_next, sj = sj_next;
        if (s + 1 < end) { e_next = g_eids[s + 1]; sj_next = srcp[e_next]; }

        const float* ep = edge_attr + (size_t)e * EDIM + 4 * lane;
        const float* fp = g_F + (size_t)sj * FW + 4 * lane;
        float4 ea = *(const float4*)ep;
        float4 kk = *(const float4*)fp;
        float4 vv = *(const float4*)(fp + 128);

        float pqk = q.x * kk.x + q.y * kk.y + q.z * kk.z + q.w * kk.w;
        float p0 = ea.x * qe0.x + ea.y * qe0.y + ea.z * qe0.z + ea.w * qe0.w;
        float p1 = ea.x * qe1.x + ea.y * qe1.y + ea.z * qe1.z + ea.w * qe1.w;
        #pragma unroll
        for (int off = 16; off >= 1; off >>= 1) {
            p0 += __shfl_xor_sync(FULL, p0, off);
            p1 += __shfl_xor_sync(FULL, p1, off);
        }
        #pragma unroll
        for (int off = 8; off >= 1; off >>= 1)
            pqk += __shfl_xor_sync(FULL, pqk, off);

        float alpha = (pqk + ((lane < 16) ? p0 : p1)) * 0.125f;

        float newmax = fmaxf(curmax, alpha);
        float scale  = __expf(curmax - newmax);
        float p      = __expf(alpha - newmax);
        curmax = newmax;

        float s0  = __shfl_sync(FULL, scale, 0);
        float s1  = __shfl_sync(FULL, scale, 16);
        float p0b = __shfl_sync(FULL, p, 0);
        float p1b = __shfl_sync(FULL, p, 16);
        float sh = (lane < 16) ? s0 : s1;
        float ph = (lane < 16) ? p0b : p1b;

        den0 = den0 * s0 + p0b;
        den1 = den1 * s1 + p1b;
        accv.x = accv.x * sh + vv.x * ph; accv.y = accv.y * sh + vv.y * ph;
        accv.z = accv.z * sh + vv.z * ph; accv.w = accv.w * sh + vv.w * ph;
        ae0.x = ae0.x * s0 + ea.x * p0b; ae0.y = ae0.y * s0 + ea.y * p0b;
        ae0.z = ae0.z * s0 + ea.z * p0b; ae0.w = ae0.w * s0 + ea.w * p0b;
        ae1.x = ae1.x * s1 + ea.x * p1b; ae1.y = ae1.y * s1 + ea.y * p1b;
        ae1.z = ae1.z * s1 + ea.z * p1b; ae1.w = ae1.w * s1 + ea.w * p1b;
    }

    float r0 = (den0 > 0.f) ? (1.f / den0) : 0.f;
    float r1 = (den1 > 0.f) ? (1.f / den1) : 0.f;
    float rh = (lane < 16) ? r0 : r1;

    float* Gi = g_G + (size_t)i * GW;
    float4 o;
    o.x = accv.x * rh; o.y = accv.y * rh; o.z = accv.z * rh; o.w = accv.w * rh;
    *(float4*)(Gi + 4 * lane) = o;
    o.x = ae0.x * r0; o.y = ae0.y * r0; o.z = ae0.z * r0; o.w = ae0.w * r0;
    *(float4*)(Gi + 128 + 4 * lane) = o;
    o.x = ae1.x * r1; o.y = ae1.y * r1; o.z = ae1.z * r1; o.w = ae1.w * r1;
    *(float4*)(Gi + 256 + 4 * lane) = o;
}

// ---------------- launch ----------------
extern "C" void kernel_launch(void* const* d_in, const int* in_sizes, int n_in,
                              void* d_out, int out_size)
{
    const float* x         = (const float*)d_in[0];
    const float* edge_attr = (const float*)d_in[1];
    const float* Wq    = (const float*)d_in[2];
    const float* bq    = (const float*)d_in[3];
    const float* Wk    = (const float*)d_in[4];
    const float* bk    = (const float*)d_in[5];
    const float* Wv    = (const float*)d_in[6];
    const float* bv    = (const float*)d_in[7];
    const float* We    = (const float*)d_in[8];
    const float* Wskip = (const float*)d_in[9];
    const float* bskip = (const float*)d_in[10];
    const float* Wproj = (const float*)d_in[11];
    const float* bproj = (const float*)d_in[12];
    const int*   eidx  = (const int*)d_in[13];
    const int*   srcp  = eidx;            // edge_index[0] = source j
    const int*   dstp  = eidx + NEDGES;   // edge_index[1] = target i

    cudaFuncSetAttribute(hmma_gemm<0>, cudaFuncAttributeMaxDynamicSharedMemorySize, GEMM_SMEM);
    cudaFuncSetAttribute(hmma_gemm<1>, cudaFuncAttributeMaxDynamicSharedMemorySize, GEMM_SMEM);

    const int NBLK = (NNODES + 127) / 128;  // 391

    // 1. fold + split weights
    prep_weights<<<(148224 + 255) / 256, 256>>>(Wq, bq, Wk, bk, Wv, bv, We,
                                                Wskip, bskip, Wproj, bproj);
    // 2. front GEMM (HMMA split-bf16): F = x @ Wbig + bbig
    hmma_gemm<0><<<NBLK, 256, GEMM_SMEM>>>(x, nullptr);
    // 3. CSR build
    zero_deg_kernel<<<(NNODES + 255) / 256, 256>>>();
    hist_kernel<<<(NEDGES + 255) / 256, 256>>>(dstp);
    scan_kernel<<<1, 1024>>>();
    scatter_kernel<<<(NEDGES + 255) / 256, 256>>>(dstp);
    // 4. per-node attention
    edge_attn_kernel<<<(NNODES * 32 + 255) / 256, 256>>>(edge_attr, srcp);
    // 5. back GEMM (HMMA split-bf16): out = [G | x] @ Wback + bback
    hmma_gemm<1><<<NBLK, 256, GEMM_SMEM>>>(x, (float*)d_out);
}

// round 11
// speedup vs baseline: 1.3306x; 1.1065x over previous
#include <cuda_runtime.h>
#include <cuda_bf16.h>
#include <math.h>
#include <stdint.h>

#define NNODES 50000
#define NEDGES 800000
#define EDIM   128

// ---------------- device scratch (no allocs allowed) ----------------
__device__ float g_KV[(size_t)NNODES * 256];    // [k(128)|v(128)]  51.2 MB (gathered)
__device__ float g_Q [(size_t)NNODES * 384];    // [q|qe0|qe1]      76.8 MB (streamed)
__device__ __nv_bfloat16 g_Ghi[(size_t)NNODES * 384];  // split-bf16 G
__device__ __nv_bfloat16 g_Glo[(size_t)NNODES * 384];
__device__ __nv_bfloat16 g_Xhi[(size_t)NNODES * 128];  // split-bf16 x
__device__ __nv_bfloat16 g_Xlo[(size_t)NNODES * 128];
__device__ int   g_deg[NNODES];
__device__ int   g_rowptr[NNODES + 1];
__device__ int   g_cursor[NNODES];
__device__ int   g_eids[NEDGES];
__device__ float g_bbig[640];
__device__ float g_bback[EDIM];
// split-bf16 weights, [out][k] K-major (mma.sync "col" B operand)
__device__ __nv_bfloat16 g_BFt_hi[640 * 128];
__device__ __nv_bfloat16 g_BFt_lo[640 * 128];
__device__ __nv_bfloat16 g_BBt_hi[128 * 512];
__device__ __nv_bfloat16 g_BBt_lo[128 * 512];

// ================= helpers =================
__device__ __forceinline__ uint32_t smem_u32(const void* p) {
    uint32_t a;
    asm("{ .reg .u64 t; cvta.to.shared.u64 t, %1; cvt.u32.u64 %0, t; }"
        : "=r"(a) : "l"(p));
    return a;
}
__device__ __forceinline__ void split2(float a, __nv_bfloat16& h, __nv_bfloat16& l)
{
    h = __float2bfloat16(a);
    l = __float2bfloat16(a - __bfloat162float(h));
}
__device__ __forceinline__ void ldsm4(uint32_t* r, uint32_t addr) {
    asm volatile("ldmatrix.sync.aligned.m8n8.x4.shared.b16 {%0,%1,%2,%3}, [%4];"
        : "=r"(r[0]), "=r"(r[1]), "=r"(r[2]), "=r"(r[3]) : "r"(addr));
}
__device__ __forceinline__ void mma16816(float* c, const uint32_t* a, const uint32_t* b) {
    asm volatile("mma.sync.aligned.m16n8k16.row.col.f32.bf16.bf16.f32 "
        "{%0,%1,%2,%3}, {%4,%5,%6,%7}, {%8,%9}, {%0,%1,%2,%3};"
        : "+f"(c[0]), "+f"(c[1]), "+f"(c[2]), "+f"(c[3])
        : "r"(a[0]), "r"(a[1]), "r"(a[2]), "r"(a[3]), "r"(b[0]), "r"(b[1]));
}
__device__ __forceinline__ void cpa16(uint32_t dst, const void* src) {
    asm volatile("cp.async.cg.shared.global [%0], [%1], 16;"
                 :: "r"(dst), "l"(src) : "memory");
}
#define CP_COMMIT() asm volatile("cp.async.commit_group;" ::: "memory")
#define CP_WAIT(n)  asm volatile("cp.async.wait_group %0;" :: "n"(n) : "memory")

// ---------------- weight preprocessing ----------------
__global__ void prep_weights(
    const float* __restrict__ Wq, const float* __restrict__ bq,
    const float* __restrict__ Wk, const float* __restrict__ bk,
    const float* __restrict__ Wv, const float* __restrict__ bv,
    const float* __restrict__ We,
    const float* __restrict__ Wskip, const float* __restrict__ bskip,
    const float* __restrict__ Wproj, const float* __restrict__ bproj)
{
    int t = blockIdx.x * blockDim.x + threadIdx.x;
    if (t < 81920) {  // front weights: (r=k, c=out)
        int r = t / 640, c = t % 640;
        float val;
        if (c < 128)      val = Wk[r * 128 + c];
        else if (c < 256) val = Wv[r * 128 + (c - 128)];
        else if (c < 384) val = Wq[r * 128 + (c - 256)];
        else {
            int cc = c - 384, h = cc >> 7, d = cc & 127;
            float s = 0.f;
            #pragma unroll 8
            for (int ci = 0; ci < 64; ci++)
                s += Wq[r * 128 + h * 64 + ci] * We[d * 128 + h * 64 + ci];
            val = s;
        }
        __nv_bfloat16 h16, l16; split2(val, h16, l16);
        g_BFt_hi[c * 128 + r] = h16;
        g_BFt_lo[c * 128 + r] = l16;
        return;
    }
    t -= 81920;
    if (t < 640) {  // bbig
        int c = t; float val;
        if (c < 128)      val = bk[c];
        else if (c < 256) val = bv[c - 128];
        else if (c < 384) val = bq[c - 256];
        else {
            int cc = c - 384, h = cc >> 7, d = cc & 127;
            float s = 0.f;
            #pragma unroll 8
            for (int ci = 0; ci < 64; ci++)
                s += bq[h * 64 + ci] * We[d * 128 + h * 64 + ci];
            val = s;
        }
        g_bbig[c] = val;
        return;
    }
    t -= 640;
    if (t < 65536) {  // back weights: (k, o)
        int k = t / 128, o = t % 128;
        float val;
        if (k < 128) {
            val = Wproj[k * 128 + o];
        } else if (k < 384) {
            int kk = k - 128, h = kk >> 7, d = kk & 127;
            float s = 0.f;
            #pragma unroll 8
            for (int ci = 0; ci < 64; ci++)
                s += We[d * 128 + h * 64 + ci] * Wproj[(h * 64 + ci) * 128 + o];
            val = s;
        } else {
            int r = k - 384;
            float s = 0.f;
            #pragma unroll 8
            for (int m = 0; m < 128; m++)
                s += Wskip[r * 128 + m] * Wproj[m * 128 + o];
            val = s;
        }
        __nv_bfloat16 h16, l16; split2(val, h16, l16);
        g_BBt_hi[o * 512 + k] = h16;
        g_BBt_lo[o * 512 + k] = l16;
        return;
    }
    t -= 65536;
    if (t < 128) {  // bback
        int o = t;
        float s = bproj[o];
        #pragma unroll 8
        for (int m = 0; m < 128; m++)
            s += bskip[m] * Wproj[m * 128 + o];
        g_bback[o] = s;
    }
}

// ---------------- x presplit ----------------
__global__ void split_x_kernel(const float* __restrict__ x)
{
    int t = blockIdx.x * blockDim.x + threadIdx.x;
    if (t >= NNODES * 32) return;
    float4 v = ((const float4*)x)[t];
    union { __nv_bfloat16 b[4]; uint2 u; } H, L;
    split2(v.x, H.b[0], L.b[0]); split2(v.y, H.b[1], L.b[1]);
    split2(v.z, H.b[2], L.b[2]); split2(v.w, H.b[3], L.b[3]);
    *(uint2*)(g_Xhi + (size_t)t * 4) = H.u;
    *(uint2*)(g_Xlo + (size_t)t * 4) = L.u;
}

// ================= HMMA split-bf16 GEMM (cp.async pipelined) =================
// mainloop: M=128 x N=128 tile, KSTEPS k16-steps, smem row stride STRIDE (16B units)
template <int KSTEPS, int STRIDE>
__device__ __forceinline__ void mainloop2(uint32_t sb,
    uint32_t offAhi, uint32_t offAlo, uint32_t offBhi, uint32_t offBlo,
    float acc[2][8][4], int wid, int lane)
{
    int wm = wid & 3, wn = wid >> 2;
    int arow  = wm * 32 + ((lane >> 3) & 1) * 8 + (lane & 7);
    int acolh = lane >> 4;
    int g = lane >> 3;
    int bnt_sub = g >> 1;   // which n8 block in the pair
    int bkh = g & 1;        // k half
    int brow_base = wn * 64 + (lane & 7);
    #pragma unroll
    for (int ks = 0; ks < KSTEPS; ks++) {
        uint32_t ah0[4], ah1[4], al0[4], al1[4];
        uint32_t au = (uint32_t)(ks * 2 + acolh);
        ldsm4(ah0, sb + offAhi + ((uint32_t)arow * STRIDE + au) * 16);
        ldsm4(ah1, sb + offAhi + ((uint32_t)(arow + 16) * STRIDE + au) * 16);
        ldsm4(al0, sb + offAlo + ((uint32_t)arow * STRIDE + au) * 16);
        ldsm4(al1, sb + offAlo + ((uint32_t)(arow + 16) * STRIDE + au) * 16);
        #pragma unroll
        for (int np = 0; np < 4; np++) {
            uint32_t bh[4], bl[4];
            uint32_t brow = (uint32_t)(brow_base + (np * 2 + bnt_sub) * 8);
            uint32_t bu = (uint32_t)(ks * 2 + bkh);
            ldsm4(bh, sb + offBhi + (brow * STRIDE + bu) * 16);
            ldsm4(bl, sb + offBlo + (brow * STRIDE + bu) * 16);
            int n0 = np * 2, n1 = np * 2 + 1;
            mma16816(acc[0][n0], ah0, bh + 0);
            mma16816(acc[1][n0], ah1, bh + 0);
            mma16816(acc[0][n1], ah0, bh + 2);
            mma16816(acc[1][n1], ah1, bh + 2);
            mma16816(acc[0][n0], ah0, bl + 0);
            mma16816(acc[1][n0], ah1, bl + 0);
            mma16816(acc[0][n1], ah0, bl + 2);
            mma16816(acc[1][n1], ah1, bl + 2);
            mma16816(acc[0][n0], al0, bh + 0);
            mma16816(acc[1][n0], al1, bh + 0);
            mma16816(acc[0][n1], al0, bh + 2);
            mma16816(acc[1][n1], al1, bh + 2);
        }
    }
}

// ---------------- front GEMM ----------------
// F = x @ Wbig + bbig; output cols 0..255 -> g_KV, 256..639 -> g_Q
#define F_STRIDE 17
#define F_MATB   (128 * F_STRIDE * 16)      // 34816 bytes per 128x128 bf16 matrix
#define F_AHI 0
#define F_ALO F_MATB
#define F_BST(s) (2 * F_MATB + (s) * 2 * F_MATB)
#define F_SMEM (6 * F_MATB)                 // 208896

__device__ __forceinline__ void front_issue_A(uint32_t sb, int m0, int tid)
{
    #pragma unroll 1
    for (int it = tid; it < 2048; it += 256) {
        int row = it >> 4, u = it & 15;
        int grow = m0 + row; if (grow >= NNODES) grow = 0;
        uint32_t off = ((uint32_t)row * F_STRIDE + (uint32_t)u) * 16;
        cpa16(sb + F_AHI + off, g_Xhi + (size_t)grow * 128 + u * 8);
        cpa16(sb + F_ALO + off, g_Xlo + (size_t)grow * 128 + u * 8);
    }
}
__device__ __forceinline__ void front_issue_B(uint32_t sb, int stage, int nt, int tid)
{
    uint32_t bb = F_BST(stage);
    #pragma unroll 1
    for (int it = tid; it < 2048; it += 256) {
        int n = it >> 4, u = it & 15;
        size_t si = (size_t)(nt * 128 + n) * 128 + u * 8;
        uint32_t off = ((uint32_t)n * F_STRIDE + (uint32_t)u) * 16;
        cpa16(sb + bb + off,          g_BFt_hi + si);
        cpa16(sb + bb + F_MATB + off, g_BFt_lo + si);
    }
}

__device__ __forceinline__ void front_epilogue(float acc[2][8][4], int tile,
                                               int m0, int wid, int lane)
{
    int n0 = tile * 128;
    int wm = wid & 3, wn = wid >> 2;
    int r = m0 + wm * 32 + (lane >> 2);
    int cbase = n0 + wn * 64 + (lane & 3) * 2;
    float* base = (tile < 2) ? g_KV : g_Q;
    int stride  = (tile < 2) ? 256 : 384;
    int csub    = (tile < 2) ? 0 : 256;
    #pragma unroll
    for (int mt = 0; mt < 2; mt++) {
        int r0 = r + mt * 16, r1 = r0 + 8;
        #pragma unroll
        for (int nt = 0; nt < 8; nt++) {
            int c = cbase + nt * 8;
            float2 bv = *(const float2*)(g_bbig + c);
            if (r0 < NNODES)
                *(float2*)(base + (size_t)r0 * stride + c - csub) =
                    make_float2(acc[mt][nt][0] + bv.x, acc[mt][nt][1] + bv.y);
            if (r1 < NNODES)
                *(float2*)(base + (size_t)r1 * stride + c - csub) =
                    make_float2(acc[mt][nt][2] + bv.x, acc[mt][nt][3] + bv.y);
        }
    }
}

__global__ void __launch_bounds__(256, 1) front_gemm()
{
    extern __shared__ char smem[];
    uint32_t sb = smem_u32(smem);
    int tid = threadIdx.x, wid = tid >> 5, lane = tid & 31;
    int m0 = blockIdx.x * 128;
    float acc[2][8][4];

    front_issue_A(sb, m0, tid);
    front_issue_B(sb, 0, 0, tid);
    CP_COMMIT();                 // g0 = A + B0
    front_issue_B(sb, 1, 1, tid);
    CP_COMMIT();                 // g1 = B1

    #pragma unroll 1
    for (int nt = 0; nt < 5; nt++) {
        if (nt < 4) { CP_WAIT(1); } else { CP_WAIT(0); }
        __syncthreads();
        #pragma unroll
        for (int a = 0; a < 2; a++)
            #pragma unroll
            for (int b = 0; b < 8; b++)
                #pragma unroll
                for (int d = 0; d < 4; d++) acc[a][b][d] = 0.f;
        int st = nt & 1;
        mainloop2<8, F_STRIDE>(sb, F_AHI, F_ALO, F_BST(st), F_BST(st) + F_MATB,
                               acc, wid, lane);
        front_epilogue(acc, nt, m0, wid, lane);
        __syncthreads();
        if (nt + 2 <= 4) {
            front_issue_B(sb, st, nt + 2, tid);
            CP_COMMIT();
        }
    }
}

// ---------------- back GEMM ----------------
// out = [G(384)|x(128)] @ Wback + bback; 8 K-chunks of 64
#define B_STRIDE 9
#define B_MATB   (128 * B_STRIDE * 16)      // 18432 bytes per 128x64 bf16 matrix
#define B_STG(s) ((s) * 4 * B_MATB)
#define B_SMEM   (8 * B_MATB)               // 147456

__device__ __forceinline__ void back_issue(uint32_t sb, int stage, int kc,
                                           int m0, int tid)
{
    uint32_t bs = B_STG(stage);
    int kbase = kc * 64;
    const __nv_bfloat16* Ah; const __nv_bfloat16* Al; int astr, aoff;
    if (kbase < 384) { Ah = g_Ghi; Al = g_Glo; astr = 384; aoff = kbase; }
    else             { Ah = g_Xhi; Al = g_Xlo; astr = 128; aoff = kbase - 384; }
    #pragma unroll 1
    for (int it = tid; it < 1024; it += 256) {
        int row = it >> 3, u = it & 7;
        int grow = m0 + row; if (grow >= NNODES) grow = 0;
        uint32_t off = ((uint32_t)row * B_STRIDE + (uint32_t)u) * 16;
        cpa16(sb + bs + off,            Ah + (size_t)grow * astr + aoff + u * 8);
        cpa16(sb + bs + B_MATB + off,   Al + (size_t)grow * astr + aoff + u * 8);
        size_t si = (size_t)row * 512 + kbase + u * 8;
        cpa16(sb + bs + 2 * B_MATB + off, g_BBt_hi + si);
        cpa16(sb + bs + 3 * B_MATB + off, g_BBt_lo + si);
    }
}

__global__ void __launch_bounds__(256, 1) back_gemm(float* __restrict__ Out)
{
    extern __shared__ char smem[];
    uint32_t sb = smem_u32(smem);
    int tid = threadIdx.x, wid = tid >> 5, lane = tid & 31;
    int m0 = blockIdx.x * 128;
    float acc[2][8][4];
    #pragma unroll
    for (int a = 0; a < 2; a++)
        #pragma unroll
        for (int b = 0; b < 8; b++)
            #pragma unroll
            for (int d = 0; d < 4; d++) acc[a][b][d] = 0.f;

    back_issue(sb, 0, 0, m0, tid); CP_COMMIT();
    back_issue(sb, 1, 1, m0, tid); CP_COMMIT();

    #pragma unroll 1
    for (int c = 0; c < 8; c++) {
        if (c < 7) { CP_WAIT(1); } else { CP_WAIT(0); }
        __syncthreads();
        int st = c & 1;
        uint32_t bs = B_STG(st);
        mainloop2<4, B_STRIDE>(sb, bs, bs + B_MATB, bs + 2 * B_MATB,
                               bs + 3 * B_MATB, acc, wid, lane);
        __syncthreads();
        if (c + 2 <= 7) {
            back_issue(sb, st, c + 2, m0, tid);
            CP_COMMIT();
        }
    }

    int wm = wid & 3, wn = wid >> 2;
    int r = m0 + wm * 32 + (lane >> 2);
    int cbase = wn * 64 + (lane & 3) * 2;
    #pragma unroll
    for (int mt = 0; mt < 2; mt++) {
        int r0 = r + mt * 16, r1 = r0 + 8;
        #pragma unroll
        for (int nt = 0; nt < 8; nt++) {
            int c = cbase + nt * 8;
            float2 bv = *(const float2*)(g_bback + c);
            if (r0 < NNODES)
                *(float2*)(Out + (size_t)r0 * 128 + c) =
                    make_float2(acc[mt][nt][0] + bv.x, acc[mt][nt][1] + bv.y);
            if (r1 < NNODES)
                *(float2*)(Out + (size_t)r1 * 128 + c) =
                    make_float2(acc[mt][nt][2] + bv.x, acc[mt][nt][3] + bv.y);
        }
    }
}

// ---------------- CSR build ----------------
__global__ void zero_deg_kernel()
{
    int t = blockIdx.x * blockDim.x + threadIdx.x;
    if (t < NNODES) g_deg[t] = 0;
}

__global__ void hist_kernel(const int* __restrict__ dst)
{
    int t = blockIdx.x * blockDim.x + threadIdx.x;
    if (t < NEDGES) atomicAdd(&g_deg[dst[t]], 1);
}

__global__ void scan_kernel()
{
    __shared__ int sm[1024];
    int t = threadIdx.x;
    const int CH = (NNODES + 1023) / 1024;  // 49
    int lo = t * CH;
    int hi = min(lo + CH, NNODES);
    int s = 0;
    for (int i = lo; i < hi; i++) s += g_deg[i];
    sm[t] = s;
    __syncthreads();
    for (int off = 1; off < 1024; off <<= 1) {
        int y = (t >= off) ? sm[t - off] : 0;
        __syncthreads();
        sm[t] += y;
        __syncthreads();
    }
    int run = sm[t] - s;  // exclusive prefix
    for (int i = lo; i < hi; i++) {
        g_rowptr[i] = run;
        g_cursor[i] = run;
        run += g_deg[i];
    }
    if (t == 1023) g_rowptr[NNODES] = sm[1023];
}

__global__ void scatter_kernel(const int* __restrict__ dst)
{
    int t = blockIdx.x * blockDim.x + threadIdx.x;
    if (t < NEDGES) {
        int d = dst[t];
        int pos = atomicAdd(&g_cursor[d], 1);
        g_eids[pos] = t;
    }
}

// ---------------- per-node attention (1 warp / node, online softmax) ----
__global__ void __launch_bounds__(256) edge_attn_kernel(
    const float* __restrict__ edge_attr, const int* __restrict__ srcp)
{
    int gw   = (blockIdx.x * blockDim.x + threadIdx.x) >> 5;
    int lane = threadIdx.x & 31;
    if (gw >= NNODES) return;
    int i = gw;
    int base = g_rowptr[i], end = g_rowptr[i + 1];
    bool lohalf = (lane < 16);

    const float* Qi = g_Q + (size_t)i * 384;
    float4 q   = *(const float4*)(Qi + 4 * lane);
    float4 qe0 = *(const float4*)(Qi + 128 + 4 * lane);
    float4 qe1 = *(const float4*)(Qi + 256 + 4 * lane);

    float4 accv = make_float4(0.f, 0.f, 0.f, 0.f);
    float4 ae0  = make_float4(0.f, 0.f, 0.f, 0.f);
    float4 ae1  = make_float4(0.f, 0.f, 0.f, 0.f);
    float den = 0.f;          // per-half (own head)
    float curmax = -3.0e38f;  // per-half
    const unsigned FULL = 0xffffffffu;

    int e_next = 0, sj_next = 0;
    if (base < end) { e_next = g_eids[base]; sj_next = srcp[e_next]; }

    for (int s = base; s < end; s++) {
        int e = e_next, sj = sj_next;
        if (s + 1 < end) { e_next = g_eids[s + 1]; sj_next = srcp[e_next]; }

        const float* ep = edge_attr + (size_t)e * EDIM + 4 * lane;
        const float* fp = g_KV + (size_t)sj * 256 + 4 * lane;
        float4 ea = *(const float4*)ep;
        float4 kk = *(const float4*)fp;
        float4 vv = *(const float4*)(fp + 128);

        float pqk = q.x * kk.x + q.y * kk.y + q.z * kk.z + q.w * kk.w;
        float p0 = ea.x * qe0.x + ea.y * qe0.y + ea.z * qe0.z + ea.w * qe0.w;
        float p1 = ea.x * qe1.x + ea.y * qe1.y + ea.z * qe1.z + ea.w * qe1.w;

        // fused reduction: per-half sum of (own-head edge term) + qk term
        float own = lohalf ? p0 : p1;
        float oth = lohalf ? p1 : p0;
        float u = own + __shfl_xor_sync(FULL, oth, 16) + pqk;
        u += __shfl_xor_sync(FULL, u, 8);
        u += __shfl_xor_sync(FULL, u, 4);
        u += __shfl_xor_sync(FULL, u, 2);
        u += __shfl_xor_sync(FULL, u, 1);
        float alpha = u * 0.125f;   // uniform within each 16-lane half

        float newmax = fmaxf(curmax, alpha);
        float scale  = __expf(curmax - newmax);
        float p      = __expf(alpha - newmax);
        curmax = newmax;
        den = den * scale + p;

        float sc_o = __shfl_xor_sync(FULL, scale, 16);
        float p_o  = __shfl_xor_sync(FULL, p, 16);
        float s0  = lohalf ? scale : sc_o;
        float s1  = lohalf ? sc_o : scale;
        float p0b = lohalf ? p : p_o;
        float p1b = lohalf ? p_o : p;

        accv.x = accv.x * scale + vv.x * p; accv.y = accv.y * scale + vv.y * p;
        accv.z = accv.z * scale + vv.z * p; accv.w = accv.w * scale + vv.w * p;
        ae0.x = ae0.x * s0 + ea.x * p0b; ae0.y = ae0.y * s0 + ea.y * p0b;
        ae0.z = ae0.z * s0 + ea.z * p0b; ae0.w = ae0.w * s0 + ea.w * p0b;
        ae1.x = ae1.x * s1 + ea.x * p1b; ae1.y = ae1.y * s1 + ea.y * p1b;
        ae1.z = ae1.z * s1 + ea.z * p1b; ae1.w = ae1.w * s1 + ea.w * p1b;
    }

    float r_own = (den > 0.f) ? (1.f / den) : 0.f;
    float r_oth = __shfl_xor_sync(FULL, r_own, 16);
    float r0 = lohalf ? r_own : r_oth;
    float r1 = lohalf ? r_oth : r_own;

    size_t gb = (size_t)i * 384;
    float4 o;
    union { __nv_bfloat16 b[4]; uint2 u2; } H, L;

    o.x = accv.x * r_own; o.y = accv.y * r_own;
    o.z = accv.z * r_own; o.w = accv.w * r_own;
    split2(o.x, H.b[0], L.b[0]); split2(o.y, H.b[1], L.b[1]);
    split2(o.z, H.b[2], L.b[2]); split2(o.w, H.b[3], L.b[3]);
    *(uint2*)(g_Ghi + gb + 4 * lane) = H.u2;
    *(uint2*)(g_Glo + gb + 4 * lane) = L.u2;

    o.x = ae0.x * r0; o.y = ae0.y * r0; o.z = ae0.z * r0; o.w = ae0.w * r0;
    split2(o.x, H.b[0], L.b[0]); split2(o.y, H.b[1], L.b[1]);
    split2(o.z, H.b[2], L.b[2]); split2(o.w, H.b[3], L.b[3]);
    *(uint2*)(g_Ghi + gb + 128 + 4 * lane) = H.u2;
    *(uint2*)(g_Glo + gb + 128 + 4 * lane) = L.u2;

    o.x = ae1.x * r1; o.y = ae1.y * r1; o.z = ae1.z * r1; o.w = ae1.w * r1;
    split2(o.x, H.b[0], L.b[0]); split2(o.y, H.b[1], L.b[1]);
    split2(o.z, H.b[2], L.b[2]); split2(o.w, H.b[3], L.b[3]);
    *(uint2*)(g_Ghi + gb + 256 + 4 * lane) = H.u2;
    *(uint2*)(g_Glo + gb + 256 + 4 * lane) = L.u2;
}

// ---------------- launch ----------------
extern "C" void kernel_launch(void* const* d_in, const int* in_sizes, int n_in,
                              void* d_out, int out_size)
{
    const float* x         = (const float*)d_in[0];
    const float* edge_attr = (const float*)d_in[1];
    const float* Wq    = (const float*)d_in[2];
    const float* bq    = (const float*)d_in[3];
    const float* Wk    = (const float*)d_in[4];
    const float* bk    = (const float*)d_in[5];
    const float* Wv    = (const float*)d_in[6];
    const float* bv    = (const float*)d_in[7];
    const float* We    = (const float*)d_in[8];
    const float* Wskip = (const float*)d_in[9];
    const float* bskip = (const float*)d_in[10];
    const float* Wproj = (const float*)d_in[11];
    const float* bproj = (const float*)d_in[12];
    const int*   eidx  = (const int*)d_in[13];
    const int*   srcp  = eidx;            // edge_index[0] = source j
    const int*   dstp  = eidx + NEDGES;   // edge_index[1] = target i

    cudaFuncSetAttribute(front_gemm, cudaFuncAttributeMaxDynamicSharedMemorySize, F_SMEM);
    cudaFuncSetAttribute(back_gemm,  cudaFuncAttributeMaxDynamicSharedMemorySize, B_SMEM);

    const int NBLK = (NNODES + 127) / 128;  // 391

    // 1. fold + split weights, split x
    prep_weights<<<(148224 + 255) / 256, 256>>>(Wq, bq, Wk, bk, Wv, bv, We,
                                                Wskip, bskip, Wproj, bproj);
    split_x_kernel<<<(NNODES * 32 + 255) / 256, 256>>>(x);
    // 2. front GEMM: [k|v] -> g_KV, [q|qe0|qe1] -> g_Q
    front_gemm<<<NBLK, 256, F_SMEM>>>();
    // 3. CSR build
    zero_deg_kernel<<<(NNODES + 255) / 256, 256>>>();
    hist_kernel<<<(NEDGES + 255) / 256, 256>>>(dstp);
    scan_kernel<<<1, 1024>>>();
    scatter_kernel<<<(NEDGES + 255) / 256, 256>>>(dstp);
    // 4. per-node attention -> split-bf16 G
    edge_attn_kernel<<<(NNODES * 32 + 255) / 256, 256>>>(edge_attr, srcp);
    // 5. back GEMM: out = [G|x] @ Wback + bback
    back_gemm<<<NBLK, 256, B_SMEM>>>((float*)d_out);
}

// round 13
// speedup vs baseline: 1.3607x; 1.0226x over previous
#include <cuda_runtime.h>
#include <cuda_bf16.h>
#include <math.h>
#include <stdint.h>

#define NNODES 50000
#define NEDGES 800000
#define EDIM   128

// ---------------- device scratch (no allocs allowed) ----------------
__device__ float g_KV[(size_t)NNODES * 256];    // [k(128)|v(128)]  51.2 MB (gathered)
__device__ float g_Q [(size_t)NNODES * 384];    // [q|qe0|qe1]      76.8 MB (streamed)
__device__ __nv_bfloat16 g_Ghi[(size_t)NNODES * 384];  // split-bf16 G
__device__ __nv_bfloat16 g_Glo[(size_t)NNODES * 384];
__device__ __nv_bfloat16 g_Xhi[(size_t)NNODES * 128];  // split-bf16 x
__device__ __nv_bfloat16 g_Xlo[(size_t)NNODES * 128];
__device__ int   g_deg[NNODES];
__device__ int   g_rowptr[NNODES + 1];
__device__ int   g_cursor[NNODES];
__device__ int   g_eids[NEDGES];
__device__ float g_bbig[640];
__device__ float g_bback[EDIM];
// split-bf16 weights, [out][k] K-major (mma.sync "col" B operand)
__device__ __nv_bfloat16 g_BFt_hi[640 * 128];
__device__ __nv_bfloat16 g_BFt_lo[640 * 128];
__device__ __nv_bfloat16 g_BBt_hi[128 * 512];
__device__ __nv_bfloat16 g_BBt_lo[128 * 512];

// ================= helpers =================
__device__ __forceinline__ uint32_t smem_u32(const void* p) {
    uint32_t a;
    asm("{ .reg .u64 t; cvta.to.shared.u64 t, %1; cvt.u32.u64 %0, t; }"
        : "=r"(a) : "l"(p));
    return a;
}
__device__ __forceinline__ void split2(float a, __nv_bfloat16& h, __nv_bfloat16& l)
{
    h = __float2bfloat16(a);
    l = __float2bfloat16(a - __bfloat162float(h));
}
__device__ __forceinline__ void ldsm4(uint32_t* r, uint32_t addr) {
    asm volatile("ldmatrix.sync.aligned.m8n8.x4.shared.b16 {%0,%1,%2,%3}, [%4];"
        : "=r"(r[0]), "=r"(r[1]), "=r"(r[2]), "=r"(r[3]) : "r"(addr));
}
__device__ __forceinline__ void mma16816(float* c, const uint32_t* a, const uint32_t* b) {
    asm volatile("mma.sync.aligned.m16n8k16.row.col.f32.bf16.bf16.f32 "
        "{%0,%1,%2,%3}, {%4,%5,%6,%7}, {%8,%9}, {%0,%1,%2,%3};"
        : "+f"(c[0]), "+f"(c[1]), "+f"(c[2]), "+f"(c[3])
        : "r"(a[0]), "r"(a[1]), "r"(a[2]), "r"(a[3]), "r"(b[0]), "r"(b[1]));
}
__device__ __forceinline__ void cpa16(uint32_t dst, const void* src) {
    asm volatile("cp.async.cg.shared.global [%0], [%1], 16;"
                 :: "r"(dst), "l"(src) : "memory");
}
#define CP_COMMIT() asm volatile("cp.async.commit_group;" ::: "memory")
#define CP_WAIT(n)  asm volatile("cp.async.wait_group %0;" :: "n"(n) : "memory")

// streaming (evict-first) loads/stores — keep g_KV resident in L2
__device__ __forceinline__ float4 ldcs128(const float* p) {
    float4 v;
    asm volatile("ld.global.cs.v4.f32 {%0,%1,%2,%3}, [%4];"
        : "=f"(v.x), "=f"(v.y), "=f"(v.z), "=f"(v.w) : "l"(p));
    return v;
}
__device__ __forceinline__ void stcs64u(void* p, uint2 v) {
    asm volatile("st.global.cs.v2.b32 [%0], {%1,%2};"
        :: "l"(p), "r"(v.x), "r"(v.y) : "memory");
}
__device__ __forceinline__ void stcs64f(void* p, float2 v) {
    asm volatile("st.global.cs.v2.f32 [%0], {%1,%2};"
        :: "l"(p), "f"(v.x), "f"(v.y) : "memory");
}

// ---------------- fused prep: split x + zero deg + fold/split weights ----
#define SPLITN (NNODES * 32)
__global__ void prep_all(
    const float* __restrict__ x,
    const float* __restrict__ Wq, const float* __restrict__ bq,
    const float* __restrict__ Wk, const float* __restrict__ bk,
    const float* __restrict__ Wv, const float* __restrict__ bv,
    const float* __restrict__ We,
    const float* __restrict__ Wskip, const float* __restrict__ bskip,
    const float* __restrict__ Wproj, const float* __restrict__ bproj)
{
    int t = blockIdx.x * blockDim.x + threadIdx.x;
    if (t < SPLITN) {   // x presplit
        float4 v = ((const float4*)x)[t];
        union { __nv_bfloat16 b[4]; uint2 u; } H, L;
        split2(v.x, H.b[0], L.b[0]); split2(v.y, H.b[1], L.b[1]);
        split2(v.z, H.b[2], L.b[2]); split2(v.w, H.b[3], L.b[3]);
        *(uint2*)(g_Xhi + (size_t)t * 4) = H.u;
        *(uint2*)(g_Xlo + (size_t)t * 4) = L.u;
        return;
    }
    t -= SPLITN;
    if (t < NNODES) { g_deg[t] = 0; return; }
    t -= NNODES;
    if (t < 81920) {  // front weights: (r=k, c=out)
        int r = t / 640, c = t % 640;
        float val;
        if (c < 128)      val = Wk[r * 128 + c];
        else if (c < 256) val = Wv[r * 128 + (c - 128)];
        else if (c < 384) val = Wq[r * 128 + (c - 256)];
        else {
            int cc = c - 384, h = cc >> 7, d = cc & 127;
            float s = 0.f;
            #pragma unroll 8
            for (int ci = 0; ci < 64; ci++)
                s += Wq[r * 128 + h * 64 + ci] * We[d * 128 + h * 64 + ci];
            val = s;
        }
        __nv_bfloat16 h16, l16; split2(val, h16, l16);
        g_BFt_hi[c * 128 + r] = h16;
        g_BFt_lo[c * 128 + r] = l16;
        return;
    }
    t -= 81920;
    if (t < 640) {  // bbig
        int c = t; float val;
        if (c < 128)      val = bk[c];
        else if (c < 256) val = bv[c - 128];
        else if (c < 384) val = bq[c - 256];
        else {
            int cc = c - 384, h = cc >> 7, d = cc & 127;
            float s = 0.f;
            #pragma unroll 8
            for (int ci = 0; ci < 64; ci++)
                s += bq[h * 64 + ci] * We[d * 128 + h * 64 + ci];
            val = s;
        }
        g_bbig[c] = val;
        return;
    }
    t -= 640;
    if (t < 65536) {  // back weights: (k, o)
        int k = t / 128, o = t % 128;
        float val;
        if (k < 128) {
            val = Wproj[k * 128 + o];
        } else if (k < 384) {
            int kk = k - 128, h = kk >> 7, d = kk & 127;
            float s = 0.f;
            #pragma unroll 8
            for (int ci = 0; ci < 64; ci++)
                s += We[d * 128 + h * 64 + ci] * Wproj[(h * 64 + ci) * 128 + o];
            val = s;
        } else {
            int r = k - 384;
            float s = 0.f;
            #pragma unroll 8
            for (int m = 0; m < 128; m++)
                s += Wskip[r * 128 + m] * Wproj[m * 128 + o];
            val = s;
        }
        __nv_bfloat16 h16, l16; split2(val, h16, l16);
        g_BBt_hi[o * 512 + k] = h16;
        g_BBt_lo[o * 512 + k] = l16;
        return;
    }
    t -= 65536;
    if (t < 128) {  // bback
        int o = t;
        float s = bproj[o];
        #pragma unroll 8
        for (int m = 0; m < 128; m++)
            s += bskip[m] * Wproj[m * 128 + o];
        g_bback[o] = s;
    }
}
#define PREP_THREADS (SPLITN + NNODES + 81920 + 640 + 65536 + 128)

// ================= HMMA split-bf16 GEMM (cp.async pipelined) =================
template <int KSTEPS, int STRIDE>
__device__ __forceinline__ void mainloop2(uint32_t sb,
    uint32_t offAhi, uint32_t offAlo, uint32_t offBhi, uint32_t offBlo,
    float acc[2][8][4], int wid, int lane)
{
    int wm = wid & 3, wn = wid >> 2;
    int arow  = wm * 32 + ((lane >> 3) & 1) * 8 + (lane & 7);
    int acolh = lane >> 4;
    int g = lane >> 3;
    int bnt_sub = g >> 1;   // which n8 block in the pair
    int bkh = g & 1;        // k half
    int brow_base = wn * 64 + (lane & 7);
    #pragma unroll
    for (int ks = 0; ks < KSTEPS; ks++) {
        uint32_t ah0[4], ah1[4], al0[4], al1[4];
        uint32_t au = (uint32_t)(ks * 2 + acolh);
        ldsm4(ah0, sb + offAhi + ((uint32_t)arow * STRIDE + au) * 16);
        ldsm4(ah1, sb + offAhi + ((uint32_t)(arow + 16) * STRIDE + au) * 16);
        ldsm4(al0, sb + offAlo + ((uint32_t)arow * STRIDE + au) * 16);
        ldsm4(al1, sb + offAlo + ((uint32_t)(arow + 16) * STRIDE + au) * 16);
        #pragma unroll
        for (int np = 0; np < 4; np++) {
            uint32_t bh[4], bl[4];
            uint32_t brow = (uint32_t)(brow_base + (np * 2 + bnt_sub) * 8);
            uint32_t bu = (uint32_t)(ks * 2 + bkh);
            ldsm4(bh, sb + offBhi + (brow * STRIDE + bu) * 16);
            ldsm4(bl, sb + offBlo + (brow * STRIDE + bu) * 16);
            int n0 = np * 2, n1 = np * 2 + 1;
            mma16816(acc[0][n0], ah0, bh + 0);
            mma16816(acc[1][n0], ah1, bh + 0);
            mma16816(acc[0][n1], ah0, bh + 2);
            mma16816(acc[1][n1], ah1, bh + 2);
            mma16816(acc[0][n0], ah0, bl + 0);
            mma16816(acc[1][n0], ah1, bl + 0);
            mma16816(acc[0][n1], ah0, bl + 2);
            mma16816(acc[1][n1], ah1, bl + 2);
            mma16816(acc[0][n0], al0, bh + 0);
            mma16816(acc[1][n0], al1, bh + 0);
            mma16816(acc[0][n1], al0, bh + 2);
            mma16816(acc[1][n1], al1, bh + 2);
        }
    }
}

// ---------------- front GEMM ----------------
#define F_STRIDE 17
#define F_MATB   (128 * F_STRIDE * 16)
#define F_AHI 0
#define F_ALO F_MATB
#define F_BST(s) (2 * F_MATB + (s) * 2 * F_MATB)
#define F_SMEM (6 * F_MATB)                 // 208896

__device__ __forceinline__ void front_issue_A(uint32_t sb, int m0, int tid)
{
    #pragma unroll 1
    for (int it = tid; it < 2048; it += 256) {
        int row = it >> 4, u = it & 15;
        int grow = m0 + row; if (grow >= NNODES) grow = 0;
        uint32_t off = ((uint32_t)row * F_STRIDE + (uint32_t)u) * 16;
        cpa16(sb + F_AHI + off, g_Xhi + (size_t)grow * 128 + u * 8);
        cpa16(sb + F_ALO + off, g_Xlo + (size_t)grow * 128 + u * 8);
    }
}
__device__ __forceinline__ void front_issue_B(uint32_t sb, int stage, int nt, int tid)
{
    uint32_t bb = F_BST(stage);
    #pragma unroll 1
    for (int it = tid; it < 2048; it += 256) {
        int n = it >> 4, u = it & 15;
        size_t si = (size_t)(nt * 128 + n) * 128 + u * 8;
        uint32_t off = ((uint32_t)n * F_STRIDE + (uint32_t)u) * 16;
        cpa16(sb + bb + off,          g_BFt_hi + si);
        cpa16(sb + bb + F_MATB + off, g_BFt_lo + si);
    }
}

__device__ __forceinline__ void front_epilogue(float acc[2][8][4], int tile,
                                               int m0, int wid, int lane)
{
    int n0 = tile * 128;
    int wm = wid & 3, wn = wid >> 2;
    int r = m0 + wm * 32 + (lane >> 2);
    int cbase = n0 + wn * 64 + (lane & 3) * 2;
    bool toKV  = (tile < 2);
    float* base = toKV ? g_KV : g_Q;
    int stride  = toKV ? 256 : 384;
    int csub    = toKV ? 0 : 256;
    #pragma unroll
    for (int mt = 0; mt < 2; mt++) {
        int r0 = r + mt * 16, r1 = r0 + 8;
        #pragma unroll
        for (int nt = 0; nt < 8; nt++) {
            int c = cbase + nt * 8;
            float2 bv = *(const float2*)(g_bbig + c);
            if (r0 < NNODES) {
                float2 o = make_float2(acc[mt][nt][0] + bv.x, acc[mt][nt][1] + bv.y);
                float* p = base + (size_t)r0 * stride + c - csub;
                if (toKV) *(float2*)p = o; else stcs64f(p, o);
            }
            if (r1 < NNODES) {
                float2 o = make_float2(acc[mt][nt][2] + bv.x, acc[mt][nt][3] + bv.y);
                float* p = base + (size_t)r1 * stride + c - csub;
                if (toKV) *(float2*)p = o; else stcs64f(p, o);
            }
        }
    }
}

__global__ void __launch_bounds__(256, 1) front_gemm()
{
    extern __shared__ char smem[];
    uint32_t sb = smem_u32(smem);
    int tid = threadIdx.x, wid = tid >> 5, lane = tid & 31;
    int m0 = blockIdx.x * 128;
    float acc[2][8][4];

    front_issue_A(sb, m0, tid);
    front_issue_B(sb, 0, 0, tid);
    CP_COMMIT();
    front_issue_B(sb, 1, 1, tid);
    CP_COMMIT();

    #pragma unroll 1
    for (int nt = 0; nt < 5; nt++) {
        if (nt < 4) { CP_WAIT(1); } else { CP_WAIT(0); }
        __syncthreads();
        #pragma unroll
        for (int a = 0; a < 2; a++)
            #pragma unroll
            for (int b = 0; b < 8; b++)
                #pragma unroll
                for (int d = 0; d < 4; d++) acc[a][b][d] = 0.f;
        int st = nt & 1;
        mainloop2<8, F_STRIDE>(sb, F_AHI, F_ALO, F_BST(st), F_BST(st) + F_MATB,
                               acc, wid, lane);
        front_epilogue(acc, nt, m0, wid, lane);
        __syncthreads();
        if (nt + 2 <= 4) {
            front_issue_B(sb, st, nt + 2, tid);
            CP_COMMIT();
        }
    }
}

// ---------------- back GEMM ----------------
#define B_STRIDE 9
#define B_MATB   (128 * B_STRIDE * 16)
#define B_STG(s) ((s) * 4 * B_MATB)
#define B_SMEM   (8 * B_MATB)               // 147456

__device__ __forceinline__ void back_issue(uint32_t sb, int stage, int kc,
                                           int m0, int tid)
{
    uint32_t bs = B_STG(stage);
    int kbase = kc * 64;
    const __nv_bfloat16* Ah; const __nv_bfloat16* Al; int astr, aoff;
    if (kbase < 384) { Ah = g_Ghi; Al = g_Glo; astr = 384; aoff = kbase; }
    else             { Ah = g_Xhi; Al = g_Xlo; astr = 128; aoff = kbase - 384; }
    #pragma unroll 1
    for (int it = tid; it < 1024; it += 256) {
        int row = it >> 3, u = it & 7;
        int grow = m0 + row; if (grow >= NNODES) grow = 0;
        uint32_t off = ((uint32_t)row * B_STRIDE + (uint32_t)u) * 16;
        cpa16(sb + bs + off,            Ah + (size_t)grow * astr + aoff + u * 8);
        cpa16(sb + bs + B_MATB + off,   Al + (size_t)grow * astr + aoff + u * 8);
        size_t si = (size_t)row * 512 + kbase + u * 8;
        cpa16(sb + bs + 2 * B_MATB + off, g_BBt_hi + si);
        cpa16(sb + bs + 3 * B_MATB + off, g_BBt_lo + si);
    }
}

__global__ void __launch_bounds__(256, 1) back_gemm(float* __restrict__ Out)
{
    extern __shared__ char smem[];
    uint32_t sb = smem_u32(smem);
    int tid = threadIdx.x, wid = tid >> 5, lane = tid & 31;
    int m0 = blockIdx.x * 128;
    float acc[2][8][4];
    #pragma unroll
    for (int a = 0; a < 2; a++)
        #pragma unroll
        for (int b = 0; b < 8; b++)
            #pragma unroll
            for (int d = 0; d < 4; d++) acc[a][b][d] = 0.f;

    back_issue(sb, 0, 0, m0, tid); CP_COMMIT();
    back_issue(sb, 1, 1, m0, tid); CP_COMMIT();

    #pragma unroll 1
    for (int c = 0; c < 8; c++) {
        if (c < 7) { CP_WAIT(1); } else { CP_WAIT(0); }
        __syncthreads();
        int st = c & 1;
        uint32_t bs = B_STG(st);
        mainloop2<4, B_STRIDE>(sb, bs, bs + B_MATB, bs + 2 * B_MATB,
                               bs + 3 * B_MATB, acc, wid, lane);
        __syncthreads();
        if (c + 2 <= 7) {
            back_issue(sb, st, c + 2, m0, tid);
            CP_COMMIT();
        }
    }

    int wm = wid & 3, wn = wid >> 2;
    int r = m0 + wm * 32 + (lane >> 2);
    int cbase = wn * 64 + (lane & 3) * 2;
    #pragma unroll
    for (int mt = 0; mt < 2; mt++) {
        int r0 = r + mt * 16, r1 = r0 + 8;
        #pragma unroll
        for (int nt = 0; nt < 8; nt++) {
            int c = cbase + nt * 8;
            float2 bv = *(const float2*)(g_bback + c);
            if (r0 < NNODES)
                *(float2*)(Out + (size_t)r0 * 128 + c) =
                    make_float2(acc[mt][nt][0] + bv.x, acc[mt][nt][1] + bv.y);
            if (r1 < NNODES)
                *(float2*)(Out + (size_t)r1 * 128 + c) =
                    make_float2(acc[mt][nt][2] + bv.x, acc[mt][nt][3] + bv.y);
        }
    }
}

// ---------------- CSR build ----------------
__global__ void hist_kernel(const int* __restrict__ dst)
{
    int t = blockIdx.x * blockDim.x + threadIdx.x;
    if (t < NEDGES) atomicAdd(&g_deg[dst[t]], 1);
}

__global__ void scan_kernel()
{
    __shared__ int sm[1024];
    int t = threadIdx.x;
    const int CH = (NNODES + 1023) / 1024;  // 49
    int lo = t * CH;
    int hi = min(lo + CH, NNODES);
    int s = 0;
    for (int i = lo; i < hi; i++) s += g_deg[i];
    sm[t] = s;
    __syncthreads();
    for (int off = 1; off < 1024; off <<= 1) {
        int y = (t >= off) ? sm[t - off] : 0;
        __syncthreads();
        sm[t] += y;
        __syncthreads();
    }
    int run = sm[t] - s;  // exclusive prefix
    for (int i = lo; i < hi; i++) {
        g_rowptr[i] = run;
        g_cursor[i] = run;
        run += g_deg[i];
    }
    if (t == 1023) g_rowptr[NNODES] = sm[1023];
}

__global__ void scatter_kernel(const int* __restrict__ dst)
{
    int t = blockIdx.x * blockDim.x + threadIdx.x;
    if (t < NEDGES) {
        int d = dst[t];
        int pos = atomicAdd(&g_cursor[d], 1);
        g_eids[pos] = t;
    }
}

// ---------------- per-node attention (1 warp / node, online softmax) ----
__global__ void __launch_bounds__(256) edge_attn_kernel(
    const float* __restrict__ edge_attr, const int* __restrict__ srcp)
{
    int gw   = (blockIdx.x * blockDim.x + threadIdx.x) >> 5;
    int lane = threadIdx.x & 31;
    if (gw >= NNODES) return;
    int i = gw;
    int base = g_rowptr[i], end = g_rowptr[i + 1];
    bool lohalf = (lane < 16);

    const float* Qi = g_Q + (size_t)i * 384;
    float4 q   = ldcs128(Qi + 4 * lane);
    float4 qe0 = ldcs128(Qi + 128 + 4 * lane);
    float4 qe1 = ldcs128(Qi + 256 + 4 * lane);

    float4 accv = make_float4(0.f, 0.f, 0.f, 0.f);
    float4 ae0  = make_float4(0.f, 0.f, 0.f, 0.f);
    float4 ae1  = make_float4(0.f, 0.f, 0.f, 0.f);
    float den = 0.f;          // per-half (own head)
    float curmax = -3.0e38f;  // per-half
    const unsigned FULL = 0xffffffffu;

    int e_next = 0, sj_next = 0;
    if (base < end) { e_next = g_eids[base]; sj_next = srcp[e_next]; }

    for (int s = base; s < end; s++) {
        int e = e_next, sj = sj_next;
        if (s + 1 < end) { e_next = g_eids[s + 1]; sj_next = srcp[e_next]; }

        const float* ep = edge_attr + (size_t)e * EDIM + 4 * lane;
        const float* fp = g_KV + (size_t)sj * 256 + 4 * lane;
        float4 ea = ldcs128(ep);                  // stream, don't pollute L2
        float4 kk = *(const float4*)fp;           // keep resident
        float4 vv = *(const float4*)(fp + 128);

        float pqk = q.x * kk.x + q.y * kk.y + q.z * kk.z + q.w * kk.w;
        float p0 = ea.x * qe0.x + ea.y * qe0.y + ea.z * qe0.z + ea.w * qe0.w;
        float p1 = ea.x * qe1.x + ea.y * qe1.y + ea.z * qe1.z + ea.w * qe1.w;

        // fused reduction: per-half sum of (own-head edge term) + qk term
        float own = lohalf ? p0 : p1;
        float oth = lohalf ? p1 : p0;
        float u = own + __shfl_xor_sync(FULL, oth, 16) + pqk;
        u += __shfl_xor_sync(FULL, u, 8);
        u += __shfl_xor_sync(FULL, u, 4);
        u += __shfl_xor_sync(FULL, u, 2);
        u += __shfl_xor_sync(FULL, u, 1);
        float alpha = u * 0.125f;   // uniform within each 16-lane half

        float newmax = fmaxf(curmax, alpha);
        float scale  = __expf(curmax - newmax);
        float p      = __expf(alpha - newmax);
        curmax = newmax;
        den = den * scale + p;

        float sc_o = __shfl_xor_sync(FULL, scale, 16);
        float p_o  = __shfl_xor_sync(FULL, p, 16);
        float s0  = lohalf ? scale : sc_o;
        float s1  = lohalf ? sc_o : scale;
        float p0b = lohalf ? p : p_o;
        float p1b = lohalf ? p_o : p;

        accv.x = accv.x * scale + vv.x * p; accv.y = accv.y * scale + vv.y * p;
        accv.z = accv.z * scale + vv.z * p; accv.w = accv.w * scale + vv.w * p;
        ae0.x = ae0.x * s0 + ea.x * p0b; ae0.y = ae0.y * s0 + ea.y * p0b;
        ae0.z = ae0.z * s0 + ea.z * p0b; ae0.w = ae0.w * s0 + ea.w * p0b;
        ae1.x = ae1.x * s1 + ea.x * p1b; ae1.y = ae1.y * s1 + ea.y * p1b;
        ae1.z = ae1.z * s1 + ea.z * p1b; ae1.w = ae1.w * s1 + ea.w * p1b;
    }

    float r_own = (den > 0.f) ? (1.f / den) : 0.f;
    float r_oth = __shfl_xor_sync(FULL, r_own, 16);
    float r0 = lohalf ? r_own : r_oth;
    float r1 = lohalf ? r_oth : r_own;

    size_t gb = (size_t)i * 384;
    float4 o;
    union { __nv_bfloat16 b[4]; uint2 u2; } H, L;

    o.x = accv.x * r_own; o.y = accv.y * r_own;
    o.z = accv.z * r_own; o.w = accv.w * r_own;
    split2(o.x, H.b[0], L.b[0]); split2(o.y, H.b[1], L.b[1]);
    split2(o.z, H.b[2], L.b[2]); split2(o.w, H.b[3], L.b[3]);
    stcs64u(g_Ghi + gb + 4 * lane, H.u2);
    stcs64u(g_Glo + gb + 4 * lane, L.u2);

    o.x = ae0.x * r0; o.y = ae0.y * r0; o.z = ae0.z * r0; o.w = ae0.w * r0;
    split2(o.x, H.b[0], L.b[0]); split2(o.y, H.b[1], L.b[1]);
    split2(o.z, H.b[2], L.b[2]); split2(o.w, H.b[3], L.b[3]);
    stcs64u(g_Ghi + gb + 128 + 4 * lane, H.u2);
    stcs64u(g_Glo + gb + 128 + 4 * lane, L.u2);

    o.x = ae1.x * r1; o.y = ae1.y * r1; o.z = ae1.z * r1; o.w = ae1.w * r1;
    split2(o.x, H.b[0], L.b[0]); split2(o.y, H.b[1], L.b[1]);
    split2(o.z, H.b[2], L.b[2]); split2(o.w, H.b[3], L.b[3]);
    stcs64u(g_Ghi + gb + 256 + 4 * lane, H.u2);
    stcs64u(g_Glo + gb + 256 + 4 * lane, L.u2);
}

// ---------------- launch ----------------
extern "C" void kernel_launch(void* const* d_in, const int* in_sizes, int n_in,
                              void* d_out, int out_size)
{
    const float* x         = (const float*)d_in[0];
    const float* edge_attr = (const float*)d_in[1];
    const float* Wq    = (const float*)d_in[2];
    const float* bq    = (const float*)d_in[3];
    const float* Wk    = (const float*)d_in[4];
    const float* bk    = (const float*)d_in[5];
    const float* Wv    = (const float*)d_in[6];
    const float* bv    = (const float*)d_in[7];
    const float* We    = (const float*)d_in[8];
    const float* Wskip = (const float*)d_in[9];
    const float* bskip = (const float*)d_in[10];
    const float* Wproj = (const float*)d_in[11];
    const float* bproj = (const float*)d_in[12];
    const int*   eidx  = (const int*)d_in[13];
    const int*   srcp  = eidx;            // edge_index[0] = source j
    const int*   dstp  = eidx + NEDGES;   // edge_index[1] = target i

    cudaFuncSetAttribute(front_gemm, cudaFuncAttributeMaxDynamicSharedMemorySize, F_SMEM);
    cudaFuncSetAttribute(back_gemm,  cudaFuncAttributeMaxDynamicSharedMemorySize, B_SMEM);

    const int NBLK = (NNODES + 127) / 128;  // 391

    // launch 0: fused prep (zero deg + split x + fold/split weights)
    prep_all<<<(PREP_THREADS + 255) / 256, 256>>>(x, Wq, bq, Wk, bk, Wv, bv,
                                                  We, Wskip, bskip, Wproj, bproj);
    // launch 1-2: CSR hist + scan (independent of prep's weight part)
    hist_kernel<<<(NEDGES + 255) / 256, 256>>>(dstp);
    scan_kernel<<<1, 1024>>>();
    // launch 3: front GEMM  (ncu capture slot)
    front_gemm<<<NBLK, 256, F_SMEM>>>();
    // launch 4: CSR scatter
    scatter_kernel<<<(NEDGES + 255) / 256, 256>>>(dstp);
    // launch 5: attention
    edge_attn_kernel<<<(NNODES * 32 + 255) / 256, 256>>>(edge_attr, srcp);
    // launch 6: back GEMM
    back_gemm<<<NBLK, 256, B_SMEM>>>((float*)d_out);
}

// round 14
// speedup vs baseline: 1.4050x; 1.0325x over previous
#include <cuda_runtime.h>
#include <cuda_bf16.h>
#include <math.h>
#include <stdint.h>

#define NNODES 50000
#define NEDGES 800000
#define EDIM   128

// ---------------- device scratch (no allocs allowed) ----------------
__device__ float g_KV[(size_t)NNODES * 256];    // [k(128)|v(128)]  51.2 MB (gathered)
__device__ float g_Q [(size_t)NNODES * 384];    // [q|qe0|qe1]      76.8 MB (streamed)
__device__ __nv_bfloat16 g_Ghi[(size_t)NNODES * 384];  // split-bf16 G
__device__ __nv_bfloat16 g_Glo[(size_t)NNODES * 384];
__device__ __nv_bfloat16 g_Xhi[(size_t)NNODES * 128];  // split-bf16 x
__device__ __nv_bfloat16 g_Xlo[(size_t)NNODES * 128];
__device__ int   g_deg[NNODES];
__device__ int   g_rowptr[NNODES + 1];
__device__ int   g_cursor[NNODES];
__device__ int   g_eids[NEDGES];
__device__ float g_bbig[640];
__device__ float g_bback[EDIM];
// split-bf16 weights, [out][k] K-major (mma.sync "col" B operand)
__device__ __nv_bfloat16 g_BFt_hi[640 * 128];
__device__ __nv_bfloat16 g_BFt_lo[640 * 128];
__device__ __nv_bfloat16 g_BBt_hi[128 * 512];
__device__ __nv_bfloat16 g_BBt_lo[128 * 512];

// ================= helpers =================
__device__ __forceinline__ uint32_t smem_u32(const void* p) {
    uint32_t a;
    asm("{ .reg .u64 t; cvta.to.shared.u64 t, %1; cvt.u32.u64 %0, t; }"
        : "=r"(a) : "l"(p));
    return a;
}
__device__ __forceinline__ void split2(float a, __nv_bfloat16& h, __nv_bfloat16& l)
{
    h = __float2bfloat16(a);
    l = __float2bfloat16(a - __bfloat162float(h));
}
__device__ __forceinline__ void ldsm4(uint32_t* r, uint32_t addr) {
    asm volatile("ldmatrix.sync.aligned.m8n8.x4.shared.b16 {%0,%1,%2,%3}, [%4];"
        : "=r"(r[0]), "=r"(r[1]), "=r"(r[2]), "=r"(r[3]) : "r"(addr));
}
__device__ __forceinline__ void mma16816(float* c, const uint32_t* a, const uint32_t* b) {
    asm volatile("mma.sync.aligned.m16n8k16.row.col.f32.bf16.bf16.f32 "
        "{%0,%1,%2,%3}, {%4,%5,%6,%7}, {%8,%9}, {%0,%1,%2,%3};"
        : "+f"(c[0]), "+f"(c[1]), "+f"(c[2]), "+f"(c[3])
        : "r"(a[0]), "r"(a[1]), "r"(a[2]), "r"(a[3]), "r"(b[0]), "r"(b[1]));
}
__device__ __forceinline__ void cpa16(uint32_t dst, const void* src) {
    asm volatile("cp.async.cg.shared.global [%0], [%1], 16;"
                 :: "r"(dst), "l"(src) : "memory");
}
#define CP_COMMIT() asm volatile("cp.async.commit_group;" ::: "memory")
#define CP_WAIT(n)  asm volatile("cp.async.wait_group %0;" :: "n"(n) : "memory")

// streaming (evict-first) loads/stores — keep g_KV resident in L2
__device__ __forceinline__ float4 ldcs128(const float* p) {
    float4 v;
    asm volatile("ld.global.cs.v4.f32 {%0,%1,%2,%3}, [%4];"
        : "=f"(v.x), "=f"(v.y), "=f"(v.z), "=f"(v.w) : "l"(p));
    return v;
}
__device__ __forceinline__ void stcs64u(void* p, uint2 v) {
    asm volatile("st.global.cs.v2.b32 [%0], {%1,%2};"
        :: "l"(p), "r"(v.x), "r"(v.y) : "memory");
}
__device__ __forceinline__ void stcs64f(void* p, float2 v) {
    asm volatile("st.global.cs.v2.f32 [%0], {%1,%2};"
        :: "l"(p), "f"(v.x), "f"(v.y) : "memory");
}

// ---------------- fused prep: split x + zero deg + fold/split weights ----
#define SPLITN (NNODES * 32)
__global__ void prep_all(
    const float* __restrict__ x,
    const float* __restrict__ Wq, const float* __restrict__ bq,
    const float* __restrict__ Wk, const float* __restrict__ bk,
    const float* __restrict__ Wv, const float* __restrict__ bv,
    const float* __restrict__ We,
    const float* __restrict__ Wskip, const float* __restrict__ bskip,
    const float* __restrict__ Wproj, const float* __restrict__ bproj)
{
    int t = blockIdx.x * blockDim.x + threadIdx.x;
    if (t < SPLITN) {   // x presplit
        float4 v = ((const float4*)x)[t];
        union { __nv_bfloat16 b[4]; uint2 u; } H, L;
        split2(v.x, H.b[0], L.b[0]); split2(v.y, H.b[1], L.b[1]);
        split2(v.z, H.b[2], L.b[2]); split2(v.w, H.b[3], L.b[3]);
        *(uint2*)(g_Xhi + (size_t)t * 4) = H.u;
        *(uint2*)(g_Xlo + (size_t)t * 4) = L.u;
        return;
    }
    t -= SPLITN;
    if (t < NNODES) { g_deg[t] = 0; return; }
    t -= NNODES;
    if (t < 81920) {  // front weights: (r=k, c=out)
        int r = t / 640, c = t % 640;
        float val;
        if (c < 128)      val = Wk[r * 128 + c];
        else if (c < 256) val = Wv[r * 128 + (c - 128)];
        else if (c < 384) val = Wq[r * 128 + (c - 256)];
        else {
            int cc = c - 384, h = cc >> 7, d = cc & 127;
            float s = 0.f;
            #pragma unroll 8
            for (int ci = 0; ci < 64; ci++)
                s += Wq[r * 128 + h * 64 + ci] * We[d * 128 + h * 64 + ci];
            val = s;
        }
        __nv_bfloat16 h16, l16; split2(val, h16, l16);
        g_BFt_hi[c * 128 + r] = h16;
        g_BFt_lo[c * 128 + r] = l16;
        return;
    }
    t -= 81920;
    if (t < 640) {  // bbig
        int c = t; float val;
        if (c < 128)      val = bk[c];
        else if (c < 256) val = bv[c - 128];
        else if (c < 384) val = bq[c - 256];
        else {
            int cc = c - 384, h = cc >> 7, d = cc & 127;
            float s = 0.f;
            #pragma unroll 8
            for (int ci = 0; ci < 64; ci++)
                s += bq[h * 64 + ci] * We[d * 128 + h * 64 + ci];
            val = s;
        }
        g_bbig[c] = val;
        return;
    }
    t -= 640;
    if (t < 65536) {  // back weights: (k, o)
        int k = t / 128, o = t % 128;
        float val;
        if (k < 128) {
            val = Wproj[k * 128 + o];
        } else if (k < 384) {
            int kk = k - 128, h = kk >> 7, d = kk & 127;
            float s = 0.f;
            #pragma unroll 8
            for (int ci = 0; ci < 64; ci++)
                s += We[d * 128 + h * 64 + ci] * Wproj[(h * 64 + ci) * 128 + o];
            val = s;
        } else {
            int r = k - 384;
            float s = 0.f;
            #pragma unroll 8
            for (int m = 0; m < 128; m++)
                s += Wskip[r * 128 + m] * Wproj[m * 128 + o];
            val = s;
        }
        __nv_bfloat16 h16, l16; split2(val, h16, l16);
        g_BBt_hi[o * 512 + k] = h16;
        g_BBt_lo[o * 512 + k] = l16;
        return;
    }
    t -= 65536;
    if (t < 128) {  // bback
        int o = t;
        float s = bproj[o];
        #pragma unroll 8
        for (int m = 0; m < 128; m++)
            s += bskip[m] * Wproj[m * 128 + o];
        g_bback[o] = s;
    }
}
#define PREP_THREADS (SPLITN + NNODES + 81920 + 640 + 65536 + 128)

// ================= HMMA split-bf16 GEMM (cp.async pipelined) =================
// 16 warps, 4x4 warp grid, 32x32 per warp. acc[2 mt][4 n8][4]
template <int KSTEPS, int STRIDE>
__device__ __forceinline__ void mainloop16(uint32_t sb,
    uint32_t offAhi, uint32_t offAlo, uint32_t offBhi, uint32_t offBlo,
    float acc[2][4][4], int wid, int lane)
{
    int wm = wid & 3, wn = wid >> 2;
    int arow  = wm * 32 + ((lane >> 3) & 1) * 8 + (lane & 7);
    int acolh = lane >> 4;
    int g = lane >> 3;
    int bnt_sub = g >> 1;   // which n8 block in the pair
    int bkh = g & 1;        // k half
    int brow_base = wn * 32 + (lane & 7);
    #pragma unroll
    for (int ks = 0; ks < KSTEPS; ks++) {
        uint32_t ah0[4], ah1[4], al0[4], al1[4];
        uint32_t au = (uint32_t)(ks * 2 + acolh);
        ldsm4(ah0, sb + offAhi + ((uint32_t)arow * STRIDE + au) * 16);
        ldsm4(ah1, sb + offAhi + ((uint32_t)(arow + 16) * STRIDE + au) * 16);
        ldsm4(al0, sb + offAlo + ((uint32_t)arow * STRIDE + au) * 16);
        ldsm4(al1, sb + offAlo + ((uint32_t)(arow + 16) * STRIDE + au) * 16);
        #pragma unroll
        for (int np = 0; np < 2; np++) {
            uint32_t bh[4], bl[4];
            uint32_t brow = (uint32_t)(brow_base + (np * 2 + bnt_sub) * 8);
            uint32_t bu = (uint32_t)(ks * 2 + bkh);
            ldsm4(bh, sb + offBhi + (brow * STRIDE + bu) * 16);
            ldsm4(bl, sb + offBlo + (brow * STRIDE + bu) * 16);
            int n0 = np * 2, n1 = np * 2 + 1;
            mma16816(acc[0][n0], ah0, bh + 0);
            mma16816(acc[1][n0], ah1, bh + 0);
            mma16816(acc[0][n1], ah0, bh + 2);
            mma16816(acc[1][n1], ah1, bh + 2);
            mma16816(acc[0][n0], ah0, bl + 0);
            mma16816(acc[1][n0], ah1, bl + 0);
            mma16816(acc[0][n1], ah0, bl + 2);
            mma16816(acc[1][n1], ah1, bl + 2);
            mma16816(acc[0][n0], al0, bh + 0);
            mma16816(acc[1][n0], al1, bh + 0);
            mma16816(acc[0][n1], al0, bh + 2);
            mma16816(acc[1][n1], al1, bh + 2);
        }
    }
}

// ---------------- front GEMM ----------------
#define F_STRIDE 17
#define F_MATB   (128 * F_STRIDE * 16)
#define F_AHI 0
#define F_ALO F_MATB
#define F_BST(s) (2 * F_MATB + (s) * 2 * F_MATB)
#define F_SMEM (6 * F_MATB)                 // 208896
#define GEMM_T 512

__device__ __forceinline__ void front_issue_A(uint32_t sb, int m0, int tid)
{
    #pragma unroll 1
    for (int it = tid; it < 2048; it += GEMM_T) {
        int row = it >> 4, u = it & 15;
        int grow = m0 + row; if (grow >= NNODES) grow = 0;
        uint32_t off = ((uint32_t)row * F_STRIDE + (uint32_t)u) * 16;
        cpa16(sb + F_AHI + off, g_Xhi + (size_t)grow * 128 + u * 8);
        cpa16(sb + F_ALO + off, g_Xlo + (size_t)grow * 128 + u * 8);
    }
}
__device__ __forceinline__ void front_issue_B(uint32_t sb, int stage, int nt, int tid)
{
    uint32_t bb = F_BST(stage);
    #pragma unroll 1
    for (int it = tid; it < 2048; it += GEMM_T) {
        int n = it >> 4, u = it & 15;
        size_t si = (size_t)(nt * 128 + n) * 128 + u * 8;
        uint32_t off = ((uint32_t)n * F_STRIDE + (uint32_t)u) * 16;
        cpa16(sb + bb + off,          g_BFt_hi + si);
        cpa16(sb + bb + F_MATB + off, g_BFt_lo + si);
    }
}

__device__ __forceinline__ void front_epilogue(float acc[2][4][4], int tile,
                                               int m0, int wid, int lane)
{
    int n0 = tile * 128;
    int wm = wid & 3, wn = wid >> 2;
    int r = m0 + wm * 32 + (lane >> 2);
    int cbase = n0 + wn * 32 + (lane & 3) * 2;
    bool toKV  = (tile < 2);
    float* base = toKV ? g_KV : g_Q;
    int stride  = toKV ? 256 : 384;
    int csub    = toKV ? 0 : 256;
    #pragma unroll
    for (int mt = 0; mt < 2; mt++) {
        int r0 = r + mt * 16, r1 = r0 + 8;
        #pragma unroll
        for (int nt = 0; nt < 4; nt++) {
            int c = cbase + nt * 8;
            float2 bv = *(const float2*)(g_bbig + c);
            if (r0 < NNODES) {
                float2 o = make_float2(acc[mt][nt][0] + bv.x, acc[mt][nt][1] + bv.y);
                float* p = base + (size_t)r0 * stride + c - csub;
                if (toKV) *(float2*)p = o; else stcs64f(p, o);
            }
            if (r1 < NNODES) {
                float2 o = make_float2(acc[mt][nt][2] + bv.x, acc[mt][nt][3] + bv.y);
                float* p = base + (size_t)r1 * stride + c - csub;
                if (toKV) *(float2*)p = o; else stcs64f(p, o);
            }
        }
    }
}

__global__ void __launch_bounds__(GEMM_T, 1) front_gemm()
{
    extern __shared__ char smem[];
    uint32_t sb = smem_u32(smem);
    int tid = threadIdx.x, wid = tid >> 5, lane = tid & 31;
    int m0 = blockIdx.x * 128;
    float acc[2][4][4];

    front_issue_A(sb, m0, tid);
    front_issue_B(sb, 0, 0, tid);
    CP_COMMIT();
    front_issue_B(sb, 1, 1, tid);
    CP_COMMIT();

    #pragma unroll 1
    for (int nt = 0; nt < 5; nt++) {
        if (nt < 4) { CP_WAIT(1); } else { CP_WAIT(0); }
        __syncthreads();
        #pragma unroll
        for (int a = 0; a < 2; a++)
            #pragma unroll
            for (int b = 0; b < 4; b++)
                #pragma unroll
                for (int d = 0; d < 4; d++) acc[a][b][d] = 0.f;
        int st = nt & 1;
        mainloop16<8, F_STRIDE>(sb, F_AHI, F_ALO, F_BST(st), F_BST(st) + F_MATB,
                                acc, wid, lane);
        front_epilogue(acc, nt, m0, wid, lane);
        __syncthreads();
        if (nt + 2 <= 4) {
            front_issue_B(sb, st, nt + 2, tid);
            CP_COMMIT();
        }
    }
}

// ---------------- back GEMM ----------------
#define B_STRIDE 9
#define B_MATB   (128 * B_STRIDE * 16)
#define B_STG(s) ((s) * 4 * B_MATB)
#define B_SMEM   (8 * B_MATB)               // 147456

__device__ __forceinline__ void back_issue(uint32_t sb, int stage, int kc,
                                           int m0, int tid)
{
    uint32_t bs = B_STG(stage);
    int kbase = kc * 64;
    const __nv_bfloat16* Ah; const __nv_bfloat16* Al; int astr, aoff;
    if (kbase < 384) { Ah = g_Ghi; Al = g_Glo; astr = 384; aoff = kbase; }
    else             { Ah = g_Xhi; Al = g_Xlo; astr = 128; aoff = kbase - 384; }
    #pragma unroll 1
    for (int it = tid; it < 1024; it += GEMM_T) {
        int row = it >> 3, u = it & 7;
        int grow = m0 + row; if (grow >= NNODES) grow = 0;
        uint32_t off = ((uint32_t)row * B_STRIDE + (uint32_t)u) * 16;
        cpa16(sb + bs + off,            Ah + (size_t)grow * astr + aoff + u * 8);
        cpa16(sb + bs + B_MATB + off,   Al + (size_t)grow * astr + aoff + u * 8);
        size_t si = (size_t)row * 512 + kbase + u * 8;
        cpa16(sb + bs + 2 * B_MATB + off, g_BBt_hi + si);
        cpa16(sb + bs + 3 * B_MATB + off, g_BBt_lo + si);
    }
}

__global__ void __launch_bounds__(GEMM_T, 1) back_gemm(float* __restrict__ Out)
{
    extern __shared__ char smem[];
    uint32_t sb = smem_u32(smem);
    int tid = threadIdx.x, wid = tid >> 5, lane = tid & 31;
    int m0 = blockIdx.x * 128;
    float acc[2][4][4];
    #pragma unroll
    for (int a = 0; a < 2; a++)
        #pragma unroll
        for (int b = 0; b < 4; b++)
            #pragma unroll
            for (int d = 0; d < 4; d++) acc[a][b][d] = 0.f;

    back_issue(sb, 0, 0, m0, tid); CP_COMMIT();
    back_issue(sb, 1, 1, m0, tid); CP_COMMIT();

    #pragma unroll 1
    for (int c = 0; c < 8; c++) {
        if (c < 7) { CP_WAIT(1); } else { CP_WAIT(0); }
        __syncthreads();
        int st = c & 1;
        uint32_t bs = B_STG(st);
        mainloop16<4, B_STRIDE>(sb, bs, bs + B_MATB, bs + 2 * B_MATB,
                                bs + 3 * B_MATB, acc, wid, lane);
        __syncthreads();
        if (c + 2 <= 7) {
            back_issue(sb, st, c + 2, m0, tid);
            CP_COMMIT();
        }
    }

    int wm = wid & 3, wn = wid >> 2;
    int r = m0 + wm * 32 + (lane >> 2);
    int cbase = wn * 32 + (lane & 3) * 2;
    #pragma unroll
    for (int mt = 0; mt < 2; mt++) {
        int r0 = r + mt * 16, r1 = r0 + 8;
        #pragma unroll
        for (int nt = 0; nt < 4; nt++) {
            int c = cbase + nt * 8;
            float2 bv = *(const float2*)(g_bback + c);
            if (r0 < NNODES)
                *(float2*)(Out + (size_t)r0 * 128 + c) =
                    make_float2(acc[mt][nt][0] + bv.x, acc[mt][nt][1] + bv.y);
            if (r1 < NNODES)
                *(float2*)(Out + (size_t)r1 * 128 + c) =
                    make_float2(acc[mt][nt][2] + bv.x, acc[mt][nt][3] + bv.y);
        }
    }
}

// ---------------- CSR build ----------------
__global__ void hist_kernel(const int* __restrict__ dst)
{
    int t = blockIdx.x * blockDim.x + threadIdx.x;
    if (t < NEDGES) atomicAdd(&g_deg[dst[t]], 1);
}

__global__ void scan_kernel()
{
    __shared__ int sm[1024];
    int t = threadIdx.x;
    const int CH = (NNODES + 1023) / 1024;  // 49
    int lo = t * CH;
    int hi = min(lo + CH, NNODES);
    int s = 0;
    for (int i = lo; i < hi; i++) s += g_deg[i];
    sm[t] = s;
    __syncthreads();
    for (int off = 1; off < 1024; off <<= 1) {
        int y = (t >= off) ? sm[t - off] : 0;
        __syncthreads();
        sm[t] += y;
        __syncthreads();
    }
    int run = sm[t] - s;  // exclusive prefix
    for (int i = lo; i < hi; i++) {
        g_rowptr[i] = run;
        g_cursor[i] = run;
        run += g_deg[i];
    }
    if (t == 1023) g_rowptr[NNODES] = sm[1023];
}

__global__ void scatter_kernel(const int* __restrict__ dst)
{
    int t = blockIdx.x * blockDim.x + threadIdx.x;
    if (t < NEDGES) {
        int d = dst[t];
        int pos = atomicAdd(&g_cursor[d], 1);
        g_eids[pos] = t;
    }
}

// ---------------- per-node attention (1 warp / node, online softmax) ----
__global__ void __launch_bounds__(256) edge_attn_kernel(
    const float* __restrict__ edge_attr, const int* __restrict__ srcp)
{
    int gw   = (blockIdx.x * blockDim.x + threadIdx.x) >> 5;
    int lane = threadIdx.x & 31;
    if (gw >= NNODES) return;
    int i = gw;
    int base = g_rowptr[i], end = g_rowptr[i + 1];
    bool lohalf = (lane < 16);

    const float* Qi = g_Q + (size_t)i * 384;
    float4 q   = ldcs128(Qi + 4 * lane);
    float4 qe0 = ldcs128(Qi + 128 + 4 * lane);
    float4 qe1 = ldcs128(Qi + 256 + 4 * lane);

    float4 accv = make_float4(0.f, 0.f, 0.f, 0.f);
    float4 ae0  = make_float4(0.f, 0.f, 0.f, 0.f);
    float4 ae1  = make_float4(0.f, 0.f, 0.f, 0.f);
    float den = 0.f;          // per-half (own head)
    float curmax = -3.0e38f;  // per-half
    const unsigned FULL = 0xffffffffu;

    int e_next = 0, sj_next = 0;
    if (base < end) { e_next = g_eids[base]; sj_next = srcp[e_next]; }

    for (int s = base; s < end; s++) {
        int e = e_next, sj = sj_next;
        if (s + 1 < end) { e_next = g_eids[s + 1]; sj_next = srcp[e_next]; }

        const float* ep = edge_attr + (size_t)e * EDIM + 4 * lane;
        const float* fp = g_KV + (size_t)sj * 256 + 4 * lane;
        float4 ea = ldcs128(ep);                  // stream, don't pollute L2
        float4 kk = *(const float4*)fp;           // keep resident
        float4 vv = *(const float4*)(fp + 128);

        float pqk = q.x * kk.x + q.y * kk.y + q.z * kk.z + q.w * kk.w;
        float p0 = ea.x * qe0.x + ea.y * qe0.y + ea.z * qe0.z + ea.w * qe0.w;
        float p1 = ea.x * qe1.x + ea.y * qe1.y + ea.z * qe1.z + ea.w * qe1.w;

        // fused reduction: per-half sum of (own-head edge term) + qk term
        float own = lohalf ? p0 : p1;
        float oth = lohalf ? p1 : p0;
        float u = own + __shfl_xor_sync(FULL, oth, 16) + pqk;
        u += __shfl_xor_sync(FULL, u, 8);
        u += __shfl_xor_sync(FULL, u, 4);
        u += __shfl_xor_sync(FULL, u, 2);
        u += __shfl_xor_sync(FULL, u, 1);
        float alpha = u * 0.125f;   // uniform within each 16-lane half

        float newmax = fmaxf(curmax, alpha);
        float scale  = __expf(curmax - newmax);
        float p      = __expf(alpha - newmax);
        curmax = newmax;
        den = den * scale + p;

        float sc_o = __shfl_xor_sync(FULL, scale, 16);
        float p_o  = __shfl_xor_sync(FULL, p, 16);
        float s0  = lohalf ? scale : sc_o;
        float s1  = lohalf ? sc_o : scale;
        float p0b = lohalf ? p : p_o;
        float p1b = lohalf ? p_o : p;

        accv.x = accv.x * scale + vv.x * p; accv.y = accv.y * scale + vv.y * p;
        accv.z = accv.z * scale + vv.z * p; accv.w = accv.w * scale + vv.w * p;
        ae0.x = ae0.x * s0 + ea.x * p0b; ae0.y = ae0.y * s0 + ea.y * p0b;
        ae0.z = ae0.z * s0 + ea.z * p0b; ae0.w = ae0.w * s0 + ea.w * p0b;
        ae1.x = ae1.x * s1 + ea.x * p1b; ae1.y = ae1.y * s1 + ea.y * p1b;
        ae1.z = ae1.z * s1 + ea.z * p1b; ae1.w = ae1.w * s1 + ea.w * p1b;
    }

    float r_own = (den > 0.f) ? (1.f / den) : 0.f;
    float r_oth = __shfl_xor_sync(FULL, r_own, 16);
    float r0 = lohalf ? r_own : r_oth;
    float r1 = lohalf ? r_oth : r_own;

    size_t gb = (size_t)i * 384;
    float4 o;
    union { __nv_bfloat16 b[4]; uint2 u2; } H, L;

    o.x = accv.x * r_own; o.y = accv.y * r_own;
    o.z = accv.z * r_own; o.w = accv.w * r_own;
    split2(o.x, H.b[0], L.b[0]); split2(o.y, H.b[1], L.b[1]);
    split2(o.z, H.b[2], L.b[2]); split2(o.w, H.b[3], L.b[3]);
    stcs64u(g_Ghi + gb + 4 * lane, H.u2);
    stcs64u(g_Glo + gb + 4 * lane, L.u2);

    o.x = ae0.x * r0; o.y = ae0.y * r0; o.z = ae0.z * r0; o.w = ae0.w * r0;
    split2(o.x, H.b[0], L.b[0]); split2(o.y, H.b[1], L.b[1]);
    split2(o.z, H.b[2], L.b[2]); split2(o.w, H.b[3], L.b[3]);
    stcs64u(g_Ghi + gb + 128 + 4 * lane, H.u2);
    stcs64u(g_Glo + gb + 128 + 4 * lane, L.u2);

    o.x = ae1.x * r1; o.y = ae1.y * r1; o.z = ae1.z * r1; o.w = ae1.w * r1;
    split2(o.x, H.b[0], L.b[0]); split2(o.y, H.b[1], L.b[1]);
    split2(o.z, H.b[2], L.b[2]); split2(o.w, H.b[3], L.b[3]);
    stcs64u(g_Ghi + gb + 256 + 4 * lane, H.u2);
    stcs64u(g_Glo + gb + 256 + 4 * lane, L.u2);
}

// ---------------- launch ----------------
extern "C" void kernel_launch(void* const* d_in, const int* in_sizes, int n_in,
                              void* d_out, int out_size)
{
    const float* x         = (const float*)d_in[0];
    const float* edge_attr = (const float*)d_in[1];
    const float* Wq    = (const float*)d_in[2];
    const float* bq    = (const float*)d_in[3];
    const float* Wk    = (const float*)d_in[4];
    const float* bk    = (const float*)d_in[5];
    const float* Wv    = (const float*)d_in[6];
    const float* bv    = (const float*)d_in[7];
    const float* We    = (const float*)d_in[8];
    const float* Wskip = (const float*)d_in[9];
    const float* bskip = (const float*)d_in[10];
    const float* Wproj = (const float*)d_in[11];
    const float* bproj = (const float*)d_in[12];
    const int*   eidx  = (const int*)d_in[13];
    const int*   srcp  = eidx;            // edge_index[0] = source j
    const int*   dstp  = eidx + NEDGES;   // edge_index[1] = target i

    cudaFuncSetAttribute(front_gemm, cudaFuncAttributeMaxDynamicSharedMemorySize, F_SMEM);
    cudaFuncSetAttribute(back_gemm,  cudaFuncAttributeMaxDynamicSharedMemorySize, B_SMEM);

    const int NBLK = (NNODES + 127) / 128;  // 391

    // launch 0: fused prep (zero deg + split x + fold/split weights)
    prep_all<<<(PREP_THREADS + 255) / 256, 256>>>(x, Wq, bq, Wk, bk, Wv, bv,
                                                  We, Wskip, bskip, Wproj, bproj);
    // launch 1-2: CSR hist + scan
    hist_kernel<<<(NEDGES + 255) / 256, 256>>>(dstp);
    scan_kernel<<<1, 1024>>>();
    // launch 3: front GEMM  (ncu capture slot)
    front_gemm<<<NBLK, GEMM_T, F_SMEM>>>();
    // launch 4: CSR scatter
    scatter_kernel<<<(NEDGES + 255) / 256, 256>>>(dstp);
    // launch 5: attention
    edge_attn_kernel<<<(NNODES * 32 + 255) / 256, 256>>>(edge_attr, srcp);
    // launch 6: back GEMM
    back_gemm<<<NBLK, GEMM_T, B_SMEM>>>((float*)d_out);
}

// round 17
// speedup vs baseline: 1.4333x; 1.0202x over previous
#include <cuda_runtime.h>
#include <cuda_bf16.h>
#include <math.h>
#include <stdint.h>

#define NNODES 50000
#define NEDGES 800000
#define EDIM   128

// ---------------- device scratch (no allocs allowed) ----------------
__device__ float g_KV[(size_t)NNODES * 256];    // [k(128)|v(128)]  51.2 MB (gathered)
__device__ float g_Q [(size_t)NNODES * 384];    // [q|qe0|qe1]      76.8 MB (streamed)
__device__ __nv_bfloat16 g_Ghi[(size_t)NNODES * 384];  // split-bf16 G
__device__ __nv_bfloat16 g_Glo[(size_t)NNODES * 384];
__device__ __nv_bfloat16 g_Xhi[(size_t)NNODES * 128];  // split-bf16 x
__device__ __nv_bfloat16 g_Xlo[(size_t)NNODES * 128];
__device__ int   g_deg[NNODES];                 // zero at load; re-zeroed by back_gemm tail
__device__ int   g_rowptr[NNODES + 1];
__device__ int   g_cursor[NNODES];
__device__ int   g_eids[NEDGES];
__device__ float g_bbig[640];
__device__ float g_bback[EDIM];
// split-bf16 weights, [out][k] K-major (mma.sync "col" B operand)
__device__ __nv_bfloat16 g_BFt_hi[640 * 128];
__device__ __nv_bfloat16 g_BFt_lo[640 * 128];
__device__ __nv_bfloat16 g_BBt_hi[128 * 512];
__device__ __nv_bfloat16 g_BBt_lo[128 * 512];

// ================= helpers =================
__device__ __forceinline__ uint32_t smem_u32(const void* p) {
    uint32_t a;
    asm("{ .reg .u64 t; cvta.to.shared.u64 t, %1; cvt.u32.u64 %0, t; }"
        : "=r"(a) : "l"(p));
    return a;
}
__device__ __forceinline__ void split2(float a, __nv_bfloat16& h, __nv_bfloat16& l)
{
    h = __float2bfloat16(a);
    l = __float2bfloat16(a - __bfloat162float(h));
}
__device__ __forceinline__ void ldsm4(uint32_t* r, uint32_t addr) {
    asm volatile("ldmatrix.sync.aligned.m8n8.x4.shared.b16 {%0,%1,%2,%3}, [%4];"
        : "=r"(r[0]), "=r"(r[1]), "=r"(r[2]), "=r"(r[3]) : "r"(addr));
}
__device__ __forceinline__ void mma16816(float* c, const uint32_t* a, const uint32_t* b) {
    asm volatile("mma.sync.aligned.m16n8k16.row.col.f32.bf16.bf16.f32 "
        "{%0,%1,%2,%3}, {%4,%5,%6,%7}, {%8,%9}, {%0,%1,%2,%3};"
        : "+f"(c[0]), "+f"(c[1]), "+f"(c[2]), "+f"(c[3])
        : "r"(a[0]), "r"(a[1]), "r"(a[2]), "r"(a[3]), "r"(b[0]), "r"(b[1]));
}
__device__ __forceinline__ void cpa16(uint32_t dst, const void* src) {
    asm volatile("cp.async.cg.shared.global [%0], [%1], 16;"
                 :: "r"(dst), "l"(src) : "memory");
}
#define CP_COMMIT() asm volatile("cp.async.commit_group;" ::: "memory")
#define CP_WAIT(n)  asm volatile("cp.async.wait_group %0;" :: "n"(n) : "memory")

// streaming (evict-first) loads/stores — keep g_KV resident in L2
__device__ __forceinline__ float4 ldcs128(const float* p) {
    float4 v;
    asm volatile("ld.global.cs.v4.f32 {%0,%1,%2,%3}, [%4];"
        : "=f"(v.x), "=f"(v.y), "=f"(v.z), "=f"(v.w) : "l"(p));
    return v;
}
__device__ __forceinline__ void stcs64u(void* p, uint2 v) {
    asm volatile("st.global.cs.v2.b32 [%0], {%1,%2};"
        :: "l"(p), "r"(v.x), "r"(v.y) : "memory");
}
__device__ __forceinline__ void stcs64f(void* p, float2 v) {
    asm volatile("st.global.cs.v2.f32 [%0], {%1,%2};"
        :: "l"(p), "f"(v.x), "f"(v.y) : "memory");
}

// ---------------- fused prep: split x + hist + fold/split weights ----------
// g_deg is zeroed at module load and re-zeroed at the tail of back_gemm,
// so every call of this kernel sees g_deg == 0.
#define SPLITN (NNODES * 32)
__global__ void prep_all(
    const float* __restrict__ x, const int* __restrict__ dst,
    const float* __restrict__ Wq, const float* __restrict__ bq,
    const float* __restrict__ Wk, const float* __restrict__ bk,
    const float* __restrict__ Wv, const float* __restrict__ bv,
    const float* __restrict__ We,
    const float* __restrict__ Wskip, const float* __restrict__ bskip,
    const float* __restrict__ Wproj, const float* __restrict__ bproj)
{
    int t = blockIdx.x * blockDim.x + threadIdx.x;
    if (t < SPLITN) {   // x presplit
        float4 v = ((const float4*)x)[t];
        union { __nv_bfloat16 b[4]; uint2 u; } H, L;
        split2(v.x, H.b[0], L.b[0]); split2(v.y, H.b[1], L.b[1]);
        split2(v.z, H.b[2], L.b[2]); split2(v.w, H.b[3], L.b[3]);
        *(uint2*)(g_Xhi + (size_t)t * 4) = H.u;
        *(uint2*)(g_Xlo + (size_t)t * 4) = L.u;
        return;
    }
    t -= SPLITN;
    if (t < NEDGES) { atomicAdd(&g_deg[dst[t]], 1); return; }  // degree hist
    t -= NEDGES;
    if (t < 81920) {  // front weights: (r=k, c=out)
        int r = t / 640, c = t % 640;
        float val;
        if (c < 128)      val = Wk[r * 128 + c];
        else if (c < 256) val = Wv[r * 128 + (c - 128)];
        else if (c < 384) val = Wq[r * 128 + (c - 256)];
        else {
            int cc = c - 384, h = cc >> 7, d = cc & 127;
            float s = 0.f;
            #pragma unroll 8
            for (int ci = 0; ci < 64; ci++)
                s += Wq[r * 128 + h * 64 + ci] * We[d * 128 + h * 64 + ci];
            val = s;
        }
        __nv_bfloat16 h16, l16; split2(val, h16, l16);
        g_BFt_hi[c * 128 + r] = h16;
        g_BFt_lo[c * 128 + r] = l16;
        return;
    }
    t -= 81920;
    if (t < 640) {  // bbig
        int c = t; float val;
        if (c < 128)      val = bk[c];
        else if (c < 256) val = bv[c - 128];
        else if (c < 384) val = bq[c - 256];
        else {
            int cc = c - 384, h = cc >> 7, d = cc & 127;
            float s = 0.f;
            #pragma unroll 8
            for (int ci = 0; ci < 64; ci++)
                s += bq[h * 64 + ci] * We[d * 128 + h * 64 + ci];
            val = s;
        }
        g_bbig[c] = val;
        return;
    }
    t -= 640;
    if (t < 65536) {  // back weights: (k, o)
        int k = t / 128, o = t % 128;
        float val;
        if (k < 128) {
            val = Wproj[k * 128 + o];
        } else if (k < 384) {
            int kk = k - 128, h = kk >> 7, d = kk & 127;
            float s = 0.f;
            #pragma unroll 8
            for (int ci = 0; ci < 64; ci++)
                s += We[d * 128 + h * 64 + ci] * Wproj[(h * 64 + ci) * 128 + o];
            val = s;
        } else {
            int r = k - 384;
            float s = 0.f;
            #pragma unroll 8
            for (int m = 0; m < 128; m++)
                s += Wskip[r * 128 + m] * Wproj[m * 128 + o];
            val = s;
        }
        __nv_bfloat16 h16, l16; split2(val, h16, l16);
        g_BBt_hi[o * 512 + k] = h16;
        g_BBt_lo[o * 512 + k] = l16;
        return;
    }
    t -= 65536;
    if (t < 128) {  // bback
        int o = t;
        float s = bproj[o];
        #pragma unroll 8
        for (int m = 0; m < 128; m++)
            s += bskip[m] * Wproj[m * 128 + o];
        g_bback[o] = s;
    }
}
#define PREP_THREADS (SPLITN + NEDGES + 81920 + 640 + 65536 + 128)

// ================= HMMA split-bf16 GEMM (cp.async pipelined) =================
// 16 warps, 4x4 warp grid, 32x32 per warp. acc[2 mt][4 n8][4]
template <int KSTEPS, int STRIDE>
__device__ __forceinline__ void mainloop16(uint32_t sb,
    uint32_t offAhi, uint32_t offAlo, uint32_t offBhi, uint32_t offBlo,
    float acc[2][4][4], int wid, int lane)
{
    int wm = wid & 3, wn = wid >> 2;
    int arow  = wm * 32 + ((lane >> 3) & 1) * 8 + (lane & 7);
    int acolh = lane >> 4;
    int g = lane >> 3;
    int bnt_sub = g >> 1;   // which n8 block in the pair
    int bkh = g & 1;        // k half
    int brow_base = wn * 32 + (lane & 7);
    #pragma unroll
    for (int ks = 0; ks < KSTEPS; ks++) {
        uint32_t ah0[4], ah1[4], al0[4], al1[4];
        uint32_t au = (uint32_t)(ks * 2 + acolh);
        ldsm4(ah0, sb + offAhi + ((uint32_t)arow * STRIDE + au) * 16);
        ldsm4(ah1, sb + offAhi + ((uint32_t)(arow + 16) * STRIDE + au) * 16);
        ldsm4(al0, sb + offAlo + ((uint32_t)arow * STRIDE + au) * 16);
        ldsm4(al1, sb + offAlo + ((uint32_t)(arow + 16) * STRIDE + au) * 16);
        #pragma unroll
        for (int np = 0; np < 2; np++) {
            uint32_t bh[4], bl[4];
            uint32_t brow = (uint32_t)(brow_base + (np * 2 + bnt_sub) * 8);
            uint32_t bu = (uint32_t)(ks * 2 + bkh);
            ldsm4(bh, sb + offBhi + (brow * STRIDE + bu) * 16);
            ldsm4(bl, sb + offBlo + (brow * STRIDE + bu) * 16);
            int n0 = np * 2, n1 = np * 2 + 1;
            mma16816(acc[0][n0], ah0, bh + 0);
            mma16816(acc[1][n0], ah1, bh + 0);
            mma16816(acc[0][n1], ah0, bh + 2);
            mma16816(acc[1][n1], ah1, bh + 2);
            mma16816(acc[0][n0], ah0, bl + 0);
            mma16816(acc[1][n0], ah1, bl + 0);
            mma16816(acc[0][n1], ah0, bl + 2);
            mma16816(acc[1][n1], ah1, bl + 2);
            mma16816(acc[0][n0], al0, bh + 0);
            mma16816(acc[1][n0], al1, bh + 0);
            mma16816(acc[0][n1], al0, bh + 2);
            mma16816(acc[1][n1], al1, bh + 2);
        }
    }
}

// ---------------- front GEMM (persistent, B-resident) ----------------
// grid (29, 5): blockIdx.y = N-tile (B resident in smem), blockIdx.x strides
// over the 391 M-blocks with a 2-stage cp.async A pipeline.
#define F_STRIDE 17
#define F_MATB   (128 * F_STRIDE * 16)      // 34816 bytes per 128x128 bf16 matrix
#define F_BHI 0
#define F_BLO F_MATB
#define F_AST(s) (2 * F_MATB + (s) * 2 * F_MATB)
#define F_SMEM (6 * F_MATB)                 // 208896
#define GEMM_T 512
#define F_CTAX 29

__device__ __forceinline__ void front_load_B(uint32_t sb, int nt, int tid)
{
    #pragma unroll 1
    for (int it = tid; it < 2048; it += GEMM_T) {
        int n = it >> 4, u = it & 15;
        size_t si = (size_t)(nt * 128 + n) * 128 + u * 8;
        uint32_t off = ((uint32_t)n * F_STRIDE + (uint32_t)u) * 16;
        cpa16(sb + F_BHI + off, g_BFt_hi + si);
        cpa16(sb + F_BLO + off, g_BFt_lo + si);
    }
}
__device__ __forceinline__ void front_issue_A(uint32_t sb, int stage, int mb, int tid)
{
    uint32_t ab = F_AST(stage);
    int m0 = mb * 128;
    #pragma unroll 1
    for (int it = tid; it < 2048; it += GEMM_T) {
        int row = it >> 4, u = it & 15;
        int grow = m0 + row; if (grow >= NNODES) grow = 0;
        uint32_t off = ((uint32_t)row * F_STRIDE + (uint32_t)u) * 16;
        cpa16(sb + ab + off,          g_Xhi + (size_t)grow * 128 + u * 8);
        cpa16(sb + ab + F_MATB + off, g_Xlo + (size_t)grow * 128 + u * 8);
    }
}

__device__ __forceinline__ void front_epilogue(float acc[2][4][4], int tile,
                                               int m0, int wid, int lane)
{
    int n0 = tile * 128;
    int wm = wid & 3, wn = wid >> 2;
    int r = m0 + wm * 32 + (lane >> 2);
    int cbase = n0 + wn * 32 + (lane & 3) * 2;
    bool toKV  = (tile < 2);
    float* base = toKV ? g_KV : g_Q;
    int stride  = toKV ? 256 : 384;
    int csub    = toKV ? 0 : 256;
    #pragma unroll
    for (int mt = 0; mt < 2; mt++) {
        int r0 = r + mt * 16, r1 = r0 + 8;
        #pragma unroll
        for (int nt = 0; nt < 4; nt++) {
            int c = cbase + nt * 8;
            float2 bv = *(const float2*)(g_bbig + c);
            if (r0 < NNODES) {
                float2 o = make_float2(acc[mt][nt][0] + bv.x, acc[mt][nt][1] + bv.y);
                float* p = base + (size_t)r0 * stride + c - csub;
                if (toKV) *(float2*)p = o; else stcs64f(p, o);
            }
            if (r1 < NNODES) {
                float2 o = make_float2(acc[mt][nt][2] + bv.x, acc[mt][nt][3] + bv.y);
                float* p = base + (size_t)r1 * stride + c - csub;
                if (toKV) *(float2*)p = o; else stcs64f(p, o);
            }
        }
    }
}

__global__ void __launch_bounds__(GEMM_T, 1) front_gemm()
{
    extern __shared__ char smem[];
    uint32_t sb = smem_u32(smem);
    int tid = threadIdx.x, wid = tid >> 5, lane = tid & 31;
    int nt = blockIdx.y, bx = blockIdx.x;
    float acc[2][4][4];

    front_load_B(sb, nt, tid);
    CP_COMMIT();                              // g0 = B
    front_issue_A(sb, 0, bx, tid);
    CP_COMMIT();                              // g1 = A(j=0)
    if (bx + F_CTAX < 391) front_issue_A(sb, 1, bx + F_CTAX, tid);
    CP_COMMIT();                              // g2 = A(j=1) (maybe empty)

    int j = 0;
    #pragma unroll 1
    for (int mb = bx; mb < 391; mb += F_CTAX, j++) {
        CP_WAIT(1);                           // B..A(j) done, A(j+1) may fly
        __syncthreads();
        #pragma unroll
        for (int a = 0; a < 2; a++)
            #pragma unroll
            for (int b = 0; b < 4; b++)
                #pragma unroll
                for (int d = 0; d < 4; d++) acc[a][b][d] = 0.f;
        int st = j & 1;
        mainloop16<8, F_STRIDE>(sb, F_AST(st), F_AST(st) + F_MATB,
                                F_BHI, F_BLO, acc, wid, lane);
        front_epilogue(acc, nt, mb * 128, wid, lane);
        __syncthreads();
        if (mb + 2 * F_CTAX < 391) front_issue_A(sb, st, mb + 2 * F_CTAX, tid);
        CP_COMMIT();                          // keep group count aligned
    }
}

// ---------------- back GEMM ----------------
#define B_STRIDE 9
#define B_MATB   (128 * B_STRIDE * 16)
#define B_STG(s) ((s) * 4 * B_MATB)
#define B_SMEM   (8 * B_MATB)               // 147456

__device__ __forceinline__ void back_issue(uint32_t sb, int stage, int kc,
                                           int m0, int tid)
{
    uint32_t bs = B_STG(stage);
    int kbase = kc * 64;
    const __nv_bfloat16* Ah; const __nv_bfloat16* Al; int astr, aoff;
    if (kbase < 384) { Ah = g_Ghi; Al = g_Glo; astr = 384; aoff = kbase; }
    else             { Ah = g_Xhi; Al = g_Xlo; astr = 128; aoff = kbase - 384; }
    #pragma unroll 1
    for (int it = tid; it < 1024; it += GEMM_T) {
        int row = it >> 3, u = it & 7;
        int grow = m0 + row; if (grow >= NNODES) grow = 0;
        uint32_t off = ((uint32_t)row * B_STRIDE + (uint32_t)u) * 16;
        cpa16(sb + bs + off,            Ah + (size_t)grow * astr + aoff + u * 8);
        cpa16(sb + bs + B_MATB + off,   Al + (size_t)grow * astr + aoff + u * 8);
        size_t si = (size_t)row * 512 + kbase + u * 8;
        cpa16(sb + bs + 2 * B_MATB + off, g_BBt_hi + si);
        cpa16(sb + bs + 3 * B_MATB + off, g_BBt_lo + si);
    }
}

__global__ void __launch_bounds__(GEMM_T, 1) back_gemm(float* __restrict__ Out)
{
    extern __shared__ char smem[];
    uint32_t sb = smem_u32(smem);
    int tid = threadIdx.x, wid = tid >> 5, lane = tid & 31;
    int m0 = blockIdx.x * 128;
    float acc[2][4][4];
    #pragma unroll
    for (int a = 0; a < 2; a++)
        #pragma unroll
        for (int b = 0; b < 4; b++)
            #pragma unroll
            for (int d = 0; d < 4; d++) acc[a][b][d] = 0.f;

    back_issue(sb, 0, 0, m0, tid); CP_COMMIT();
    back_issue(sb, 1, 1, m0, tid); CP_COMMIT();

    #pragma unroll 1
    for (int c = 0; c < 8; c++) {
        if (c < 7) { CP_WAIT(1); } else { CP_WAIT(0); }
        __syncthreads();
        int st = c & 1;
        uint32_t bs = B_STG(st);
        mainloop16<4, B_STRIDE>(sb, bs, bs + B_MATB, bs + 2 * B_MATB,
                                bs + 3 * B_MATB, acc, wid, lane);
        __syncthreads();
        if (c + 2 <= 7) {
            back_issue(sb, st, c + 2, m0, tid);
            CP_COMMIT();
        }
    }

    int wm = wid & 3, wn = wid >> 2;
    int r = m0 + wm * 32 + (lane >> 2);
    int cbase = wn * 32 + (lane & 3) * 2;
    #pragma unroll
    for (int mt = 0; mt < 2; mt++) {
        int r0 = r + mt * 16, r1 = r0 + 8;
        #pragma unroll
        for (int nt = 0; nt < 4; nt++) {
            int c = cbase + nt * 8;
            float2 bv = *(const float2*)(g_bback + c);
            if (r0 < NNODES)
                *(float2*)(Out + (size_t)r0 * 128 + c) =
                    make_float2(acc[mt][nt][0] + bv.x, acc[mt][nt][1] + bv.y);
            if (r1 < NNODES)
                *(float2*)(Out + (size_t)r1 * 128 + c) =
                    make_float2(acc[mt][nt][2] + bv.x, acc[mt][nt][3] + bv.y);
        }
    }

    // re-zero degree histogram for the next kernel_launch call
    for (int t = blockIdx.x * blockDim.x + threadIdx.x; t < NNODES;
         t += gridDim.x * blockDim.x)
        g_deg[t] = 0;
}

// ---------------- CSR build ----------------
__global__ void scan_kernel()
{
    __shared__ int sm[1024];
    int t = threadIdx.x;
    const int CH = (NNODES + 1023) / 1024;  // 49
    int lo = t * CH;
    int hi = min(lo + CH, NNODES);
    int s = 0;
    for (int i = lo; i < hi; i++) s += g_deg[i];
    sm[t] = s;
    __syncthreads();
    for (int off = 1; off < 1024; off <<= 1) {
        int y = (t >= off) ? sm[t - off] : 0;
        __syncthreads();
        sm[t] += y;
        __syncthreads();
    }
    int run = sm[t] - s;  // exclusive prefix
    for (int i = lo; i < hi; i++) {
        g_rowptr[i] = run;
        g_cursor[i] = run;
        run += g_deg[i];
    }
    if (t == 1023) g_rowptr[NNODES] = sm[1023];
}

__global__ void scatter_kernel(const int* __restrict__ dst)
{
    int t = blockIdx.x * blockDim.x + threadIdx.x;
    if (t < NEDGES) {
        int d = dst[t];
        int pos = atomicAdd(&g_cursor[d], 1);
        g_eids[pos] = t;
    }
}

// ---------------- per-node attention (1 warp / node, online softmax) ----
__global__ void __launch_bounds__(256) edge_attn_kernel(
    const float* __restrict__ edge_attr, const int* __restrict__ srcp)
{
    int gw   = (blockIdx.x * blockDim.x + threadIdx.x) >> 5;
    int lane = threadIdx.x & 31;
    if (gw >= NNODES) return;
    int i = gw;
    int base = g_rowptr[i], end = g_rowptr[i + 1];
    bool lohalf = (lane < 16);

    const float* Qi = g_Q + (size_t)i * 384;
    float4 q   = ldcs128(Qi + 4 * lane);
    float4 qe0 = ldcs128(Qi + 128 + 4 * lane);
    float4 qe1 = ldcs128(Qi + 256 + 4 * lane);

    float4 accv = make_float4(0.f, 0.f, 0.f, 0.f);
    float4 ae0  = make_float4(0.f, 0.f, 0.f, 0.f);
    float4 ae1  = make_float4(0.f, 0.f, 0.f, 0.f);
    float den = 0.f;          // per-half (own head)
    float curmax = -3.0e38f;  // per-half
    const unsigned FULL = 0xffffffffu;

    int e_next = 0, sj_next = 0;
    if (base < end) { e_next = g_eids[base]; sj_next = srcp[e_next]; }

    for (int s = base; s < end; s++) {
        int e = e_next, sj = sj_next;
        if (s + 1 < end) { e_next = g_eids[s + 1]; sj_next = srcp[e_next]; }

        const float* ep = edge_attr + (size_t)e * EDIM + 4 * lane;
        const float* fp = g_KV + (size_t)sj * 256 + 4 * lane;
        float4 ea = ldcs128(ep);                  // stream, don't pollute L2
        float4 kk = *(const float4*)fp;           // keep resident
        float4 vv = *(const float4*)(fp + 128);

        float pqk = q.x * kk.x + q.y * kk.y + q.z * kk.z + q.w * kk.w;
        float p0 = ea.x * qe0.x + ea.y * qe0.y + ea.z * qe0.z + ea.w * qe0.w;
        float p1 = ea.x * qe1.x + ea.y * qe1.y + ea.z * qe1.z + ea.w * qe1.w;

        // fused reduction: per-half sum of (own-head edge term) + qk term
        float own = lohalf ? p0 : p1;
        float oth = lohalf ? p1 : p0;
        float u = own + __shfl_xor_sync(FULL, oth, 16) + pqk;
        u += __shfl_xor_sync(FULL, u, 8);
        u += __shfl_xor_sync(FULL, u, 4);
        u += __shfl_xor_sync(FULL, u, 2);
        u += __shfl_xor_sync(FULL, u, 1);
        float alpha = u * 0.125f;   // uniform within each 16-lane half

        float newmax = fmaxf(curmax, alpha);
        float scale  = __expf(curmax - newmax);
        float p      = __expf(alpha - newmax);
        curmax = newmax;
        den = den * scale + p;

        float sc_o = __shfl_xor_sync(FULL, scale, 16);
        float p_o  = __shfl_xor_sync(FULL, p, 16);
        float s0  = lohalf ? scale : sc_o;
        float s1  = lohalf ? sc_o : scale;
        float p0b = lohalf ? p : p_o;
        float p1b = lohalf ? p_o : p;

        accv.x = accv.x * scale + vv.x * p; accv.y = accv.y * scale + vv.y * p;
        accv.z = accv.z * scale + vv.z * p; accv.w = accv.w * scale + vv.w * p;
        ae0.x = ae0.x * s0 + ea.x * p0b; ae0.y = ae0.y * s0 + ea.y * p0b;
        ae0.z = ae0.z * s0 + ea.z * p0b; ae0.w = ae0.w * s0 + ea.w * p0b;
        ae1.x = ae1.x * s1 + ea.x * p1b; ae1.y = ae1.y * s1 + ea.y * p1b;
        ae1.z = ae1.z * s1 + ea.z * p1b; ae1.w = ae1.w * s1 + ea.w * p1b;
    }

    float r_own = (den > 0.f) ? (1.f / den) : 0.f;
    float r_oth = __shfl_xor_sync(FULL, r_own, 16);
    float r0 = lohalf ? r_own : r_oth;
    float r1 = lohalf ? r_oth : r_own;

    size_t gb = (size_t)i * 384;
    float4 o;
    union { __nv_bfloat16 b[4]; uint2 u2; } H, L;

    o.x = accv.x * r_own; o.y = accv.y * r_own;
    o.z = accv.z * r_own; o.w = accv.w * r_own;
    split2(o.x, H.b[0], L.b[0]); split2(o.y, H.b[1], L.b[1]);
    split2(o.z, H.b[2], L.b[2]); split2(o.w, H.b[3], L.b[3]);
    stcs64u(g_Ghi + gb + 4 * lane, H.u2);
    stcs64u(g_Glo + gb + 4 * lane, L.u2);

    o.x = ae0.x * r0; o.y = ae0.y * r0; o.z = ae0.z * r0; o.w = ae0.w * r0;
    split2(o.x, H.b[0], L.b[0]); split2(o.y, H.b[1], L.b[1]);
    split2(o.z, H.b[2], L.b[2]); split2(o.w, H.b[3], L.b[3]);
    stcs64u(g_Ghi + gb + 128 + 4 * lane, H.u2);
    stcs64u(g_Glo + gb + 128 + 4 * lane, L.u2);

    o.x = ae1.x * r1; o.y = ae1.y * r1; o.z = ae1.z * r1; o.w = ae1.w * r1;
    split2(o.x, H.b[0], L.b[0]); split2(o.y, H.b[1], L.b[1]);
    split2(o.z, H.b[2], L.b[2]); split2(o.w, H.b[3], L.b[3]);
    stcs64u(g_Ghi + gb + 256 + 4 * lane, H.u2);
    stcs64u(g_Glo + gb + 256 + 4 * lane, L.u2);
}

// ---------------- launch ----------------
extern "C" void kernel_launch(void* const* d_in, const int* in_sizes, int n_in,
                              void* d_out, int out_size)
{
    const float* x         = (const float*)d_in[0];
    const float* edge_attr = (const float*)d_in[1];
    const float* Wq    = (const float*)d_in[2];
    const float* bq    = (const float*)d_in[3];
    const float* Wk    = (const float*)d_in[4];
    const float* bk    = (const float*)d_in[5];
    const float* Wv    = (const float*)d_in[6];
    const float* bv    = (const float*)d_in[7];
    const float* We    = (const float*)d_in[8];
    const float* Wskip = (const float*)d_in[9];
    const float* bskip = (const float*)d_in[10];
    const float* Wproj = (const float*)d_in[11];
    const float* bproj = (const float*)d_in[12];
    const int*   eidx  = (const int*)d_in[13];
    const int*   srcp  = eidx;            // edge_index[0] = source j
    const int*   dstp  = eidx + NEDGES;   // edge_index[1] = target i

    cudaFuncSetAttribute(front_gemm, cudaFuncAttributeMaxDynamicSharedMemorySize, F_SMEM);
    cudaFuncSetAttribute(back_gemm,  cudaFuncAttributeMaxDynamicSharedMemorySize, B_SMEM);

    const int NBLK = (NNODES + 127) / 128;  // 391

    // launch 0: fused prep (split x + degree hist + fold/split weights)
    prep_all<<<(PREP_THREADS + 255) / 256, 256>>>(x, dstp, Wq, bq, Wk, bk,
                                                  Wv, bv, We, Wskip, bskip,
                                                  Wproj, bproj);
    // launch 1-2: CSR scan + scatter
    scan_kernel<<<1, 1024>>>();
    scatter_kernel<<<(NEDGES + 255) / 256, 256>>>(dstp);
    // launch 3: front GEMM (persistent, B-resident)  — ncu capture slot
    front_gemm<<<dim3(F_CTAX, 5), GEMM_T, F_SMEM>>>();
    // launch 4: attention
    edge_attn_kernel<<<(NNODES * 32 + 255) / 256, 256>>>(edge_attr, srcp);
    // launch 5: back GEMM (+ deg re-zero tail)
    back_gemm<<<NBLK, GEMM_T, B_SMEM>>>((float*)d_out);
}